// round 1
// baseline (speedup 1.0000x reference)
#include <cuda_runtime.h>
#include <math.h>

#define NN   100000
#define NE   1600000
#define IND  256
#define HID  128
#define NL   4
#define OUTD 7
#define LN_EPS 1e-5f

// ---------------- scratch (device globals: no allocation allowed) ----------------
__device__ float g_h0[(size_t)NN * HID];
__device__ float g_h [(size_t)NN * HID];
__device__ float g_sup[(size_t)NN * HID];
__device__ float g_s[NN];
__device__ float g_dis[NN];
__device__ int   g_cnt[NN];
__device__ int   g_cursor[NN];
__device__ int   g_rowptr[NN + 1];
__device__ int   g_colw[NE];
__device__ float g_eww[NE];

// ---------------- graph preprocessing ----------------
__global__ void k_zero(int* cnt, int* cursor) {
    int i = blockIdx.x * blockDim.x + threadIdx.x;
    if (i < NN) { cnt[i] = 0; cursor[i] = 0; }
}

__global__ void k_hist(const int* __restrict__ row, int* __restrict__ cnt) {
    int i = blockIdx.x * blockDim.x + threadIdx.x;
    if (i < NE) atomicAdd(&cnt[row[i]], 1);
}

__global__ void k_dis(const int* __restrict__ cnt, float* __restrict__ dis) {
    int i = blockIdx.x * blockDim.x + threadIdx.x;
    if (i < NN) {
        int c = cnt[i];
        float dg = (c == 0) ? 1.0f : (float)c;
        dis[i] = rsqrtf(dg);
    }
}

// single-block exclusive scan of cnt -> rowptr
__global__ void k_scan(const int* __restrict__ cnt, int* __restrict__ rowptr) {
    __shared__ int sm[1024];
    const int t = threadIdx.x;
    const int CH = (NN + 1023) / 1024;
    int lo = t * CH;
    int hi = lo + CH; if (hi > NN) hi = NN;
    int s = 0;
    for (int i = lo; i < hi; i++) s += cnt[i];
    sm[t] = s;
    __syncthreads();
    // Hillis-Steele inclusive scan
    for (int off = 1; off < 1024; off <<= 1) {
        int v = (t >= off) ? sm[t - off] : 0;
        __syncthreads();
        sm[t] += v;
        __syncthreads();
    }
    int run = (t == 0) ? 0 : sm[t - 1];
    for (int i = lo; i < hi; i++) { rowptr[i] = run; run += cnt[i]; }
    if (t == 1023) rowptr[NN] = NE;
}

__global__ void k_scatter(const int* __restrict__ row, const int* __restrict__ col,
                          const int* __restrict__ rowptr, int* __restrict__ cursor,
                          const float* __restrict__ dis,
                          int* __restrict__ colw, float* __restrict__ eww) {
    int i = blockIdx.x * blockDim.x + threadIdx.x;
    if (i < NE) {
        int r = row[i], c = col[i];
        int pos = rowptr[r] + atomicAdd(&cursor[r], 1);
        colw[pos] = c;
        eww[pos] = dis[r] * dis[c];
    }
}

// ---------------- gate: s = sigmoid(h @ q_w + q_b - 1) ----------------
__global__ void k_gate(const float* __restrict__ h, const float* __restrict__ qw,
                       const float* __restrict__ qb, float* __restrict__ s) {
    int wid = (blockIdx.x * blockDim.x + threadIdx.x) >> 5;
    int lane = threadIdx.x & 31;
    if (wid >= NN) return;
    const float4 hv = *reinterpret_cast<const float4*>(h + (size_t)wid * HID + lane * 4);
    const float4 qv = *reinterpret_cast<const float4*>(qw + lane * 4);
    float d = hv.x * qv.x + hv.y * qv.y + hv.z * qv.z + hv.w * qv.w;
    #pragma unroll
    for (int off = 16; off > 0; off >>= 1) d += __shfl_xor_sync(0xffffffffu, d, off);
    if (lane == 0) {
        float z = d + qb[0] - 1.0f;
        s[wid] = 1.0f / (1.0f + expf(-z));
    }
}

// ---------------- SpMM + AOR blend: sup = (1-s)*A_norm@h + s*h0 ----------------
__global__ void k_spmm(const float* __restrict__ h, const float* __restrict__ h0,
                       const float* __restrict__ s, const int* __restrict__ rowptr,
                       const int* __restrict__ colw, const float* __restrict__ eww,
                       float* __restrict__ sup) {
    int wid = (blockIdx.x * blockDim.x + threadIdx.x) >> 5;
    int lane = threadIdx.x & 31;
    if (wid >= NN) return;
    int start = rowptr[wid], end = rowptr[wid + 1];
    float ax = 0.f, ay = 0.f, az = 0.f, aw = 0.f;
    for (int e0 = start; e0 < end; e0 += 32) {
        int n = end - e0; if (n > 32) n = 32;
        int c = 0; float w = 0.f;
        if (lane < n) { c = colw[e0 + lane]; w = eww[e0 + lane]; }
        for (int j = 0; j < n; j++) {
            int cj   = __shfl_sync(0xffffffffu, c, j);
            float wj = __shfl_sync(0xffffffffu, w, j);
            const float4 hv = *reinterpret_cast<const float4*>(h + (size_t)cj * HID + lane * 4);
            ax += wj * hv.x; ay += wj * hv.y; az += wj * hv.z; aw += wj * hv.w;
        }
    }
    float sr = s[wid];
    float om = 1.0f - sr;
    const float4 h0v = *reinterpret_cast<const float4*>(h0 + (size_t)wid * HID + lane * 4);
    float4 o;
    o.x = om * ax + sr * h0v.x;
    o.y = om * ay + sr * h0v.y;
    o.z = om * az + sr * h0v.z;
    o.w = om * aw + sr * h0v.w;
    *reinterpret_cast<float4*>(sup + (size_t)wid * HID + lane * 4) = o;
}

// ---------------- fused GEMM + epilogue ----------------
// PROJ  : out = LN(A @ W + bias)
// !PROJ : out = LN(relu(theta*(A@W) + (1-theta)*A))      (A is "support", width 128)
template<int K, bool PROJ>
__launch_bounds__(256)
__global__ void k_gemm(const float* __restrict__ A, const float* __restrict__ W,
                       const float* __restrict__ bias, const float* __restrict__ gamma,
                       const float* __restrict__ beta, float theta,
                       float* __restrict__ out) {
    __shared__ float As[64][33];
    __shared__ float Ws[32][HID];
    const int tid = threadIdx.x;
    const int tx = tid & 31, ty = tid >> 5;
    const int r0 = blockIdx.x * 64;

    float acc[8][4];
    #pragma unroll
    for (int i = 0; i < 8; i++)
        #pragma unroll
        for (int j = 0; j < 4; j++) acc[i][j] = 0.f;

    for (int kt = 0; kt < K; kt += 32) {
        #pragma unroll
        for (int idx = tid; idx < 64 * 32; idx += 256) {
            int r = idx >> 5, k = idx & 31;
            As[r][k] = (r0 + r < NN) ? A[(size_t)(r0 + r) * K + kt + k] : 0.f;
        }
        #pragma unroll
        for (int idx = tid; idx < 32 * HID; idx += 256) {
            int kk = idx >> 7, c = idx & 127;
            Ws[kk][c] = W[(size_t)(kt + kk) * HID + c];
        }
        __syncthreads();
        #pragma unroll
        for (int k = 0; k < 32; k++) {
            float4 b4 = *reinterpret_cast<const float4*>(&Ws[k][tx * 4]);
            #pragma unroll
            for (int i = 0; i < 8; i++) {
                float a = As[ty * 8 + i][k];
                acc[i][0] += a * b4.x;
                acc[i][1] += a * b4.y;
                acc[i][2] += a * b4.z;
                acc[i][3] += a * b4.w;
            }
        }
        __syncthreads();
    }

    const float4 g4  = *reinterpret_cast<const float4*>(gamma + tx * 4);
    const float4 be4 = *reinterpret_cast<const float4*>(beta  + tx * 4);
    float4 bb4 = make_float4(0.f, 0.f, 0.f, 0.f);
    if (PROJ) bb4 = *reinterpret_cast<const float4*>(bias + tx * 4);
    const float om = 1.0f - theta;

    #pragma unroll
    for (int i = 0; i < 8; i++) {
        int r = r0 + ty * 8 + i;
        if (r >= NN) break;  // uniform within warp
        float v[4];
        if (PROJ) {
            v[0] = acc[i][0] + bb4.x; v[1] = acc[i][1] + bb4.y;
            v[2] = acc[i][2] + bb4.z; v[3] = acc[i][3] + bb4.w;
        } else {
            const float4 sv = *reinterpret_cast<const float4*>(A + (size_t)r * HID + tx * 4);
            v[0] = fmaxf(theta * acc[i][0] + om * sv.x, 0.f);
            v[1] = fmaxf(theta * acc[i][1] + om * sv.y, 0.f);
            v[2] = fmaxf(theta * acc[i][2] + om * sv.z, 0.f);
            v[3] = fmaxf(theta * acc[i][3] + om * sv.w, 0.f);
        }
        float sum = v[0] + v[1] + v[2] + v[3];
        float sq  = v[0] * v[0] + v[1] * v[1] + v[2] * v[2] + v[3] * v[3];
        #pragma unroll
        for (int off = 16; off > 0; off >>= 1) {
            sum += __shfl_xor_sync(0xffffffffu, sum, off);
            sq  += __shfl_xor_sync(0xffffffffu, sq,  off);
        }
        float mu  = sum * (1.0f / 128.0f);
        float var = sq * (1.0f / 128.0f) - mu * mu;
        var = fmaxf(var, 0.f);
        float rs = rsqrtf(var + LN_EPS);
        float4 o;
        o.x = g4.x * (v[0] - mu) * rs + be4.x;
        o.y = g4.y * (v[1] - mu) * rs + be4.y;
        o.z = g4.z * (v[2] - mu) * rs + be4.z;
        o.w = g4.w * (v[3] - mu) * rs + be4.w;
        *reinterpret_cast<float4*>(out + (size_t)r * HID + tx * 4) = o;
    }
}

// ---------------- classifier: out = h @ cls_w + cls_b ----------------
__global__ void k_cls(const float* __restrict__ h, const float* __restrict__ cw,
                      const float* __restrict__ cb, float* __restrict__ out) {
    __shared__ float wsm[HID * OUTD];
    __shared__ float bsm[OUTD];
    for (int i = threadIdx.x; i < HID * OUTD; i += blockDim.x) wsm[i] = cw[i];
    if (threadIdx.x < OUTD) bsm[threadIdx.x] = cb[threadIdx.x];
    __syncthreads();

    int wid = (blockIdx.x * blockDim.x + threadIdx.x) >> 5;
    int lane = threadIdx.x & 31;
    if (wid >= NN) return;
    const float4 hv = *reinterpret_cast<const float4*>(h + (size_t)wid * HID + lane * 4);
    float hvv[4] = {hv.x, hv.y, hv.z, hv.w};
    float p[OUTD];
    #pragma unroll
    for (int j = 0; j < OUTD; j++) p[j] = 0.f;
    #pragma unroll
    for (int t = 0; t < 4; t++) {
        int k = lane * 4 + t;
        #pragma unroll
        for (int j = 0; j < OUTD; j++) p[j] += hvv[t] * wsm[k * OUTD + j];
    }
    #pragma unroll
    for (int off = 16; off > 0; off >>= 1)
        #pragma unroll
        for (int j = 0; j < OUTD; j++) p[j] += __shfl_xor_sync(0xffffffffu, p[j], off);
    if (lane == 0) {
        #pragma unroll
        for (int j = 0; j < OUTD; j++) out[(size_t)wid * OUTD + j] = p[j] + bsm[j];
    }
}

// ---------------- launch ----------------
extern "C" void kernel_launch(void* const* d_in, const int* in_sizes, int n_in,
                              void* d_out, int out_size) {
    const float* x      = (const float*)d_in[0];
    const int*   ei     = (const int*)d_in[1];
    const float* W_proj = (const float*)d_in[2];
    const float* b_proj = (const float*)d_in[3];
    const float* gamma  = (const float*)d_in[4];
    const float* beta   = (const float*)d_in[5];
    const float* q_w    = (const float*)d_in[6];
    const float* q_b    = (const float*)d_in[7];
    const float* conv_w = (const float*)d_in[8];
    const float* cls_w  = (const float*)d_in[9];
    const float* cls_b  = (const float*)d_in[10];
    float* out = (float*)d_out;

    const int* row = ei;
    const int* col = ei + NE;

    float *h0, *h, *sup, *s, *dis, *eww;
    int *cnt, *cursor, *rowptr, *colw;
    cudaGetSymbolAddress((void**)&h0, g_h0);
    cudaGetSymbolAddress((void**)&h, g_h);
    cudaGetSymbolAddress((void**)&sup, g_sup);
    cudaGetSymbolAddress((void**)&s, g_s);
    cudaGetSymbolAddress((void**)&dis, g_dis);
    cudaGetSymbolAddress((void**)&cnt, g_cnt);
    cudaGetSymbolAddress((void**)&cursor, g_cursor);
    cudaGetSymbolAddress((void**)&rowptr, g_rowptr);
    cudaGetSymbolAddress((void**)&colw, g_colw);
    cudaGetSymbolAddress((void**)&eww, g_eww);

    const int TB = 256;
    const int gN  = (NN + TB - 1) / TB;
    const int gE  = (NE + TB - 1) / TB;
    const int gW  = (NN * 32 + TB - 1) / TB;   // warp-per-row grids
    const int gG  = (NN + 63) / 64;            // gemm grid

    // graph preprocessing (CSR build)
    k_zero<<<gN, TB>>>(cnt, cursor);
    k_hist<<<gE, TB>>>(row, cnt);
    k_dis<<<gN, TB>>>(cnt, dis);
    k_scan<<<1, 1024>>>(cnt, rowptr);
    k_scatter<<<gE, TB>>>(row, col, rowptr, cursor, dis, colw, eww);

    // h0 = LN(x @ W_proj + b_proj)
    k_gemm<IND, true><<<gG, 256>>>(x, W_proj, b_proj, gamma, beta, 0.f, h0);

    const float* hcur = h0;
    for (int i = 0; i < NL; i++) {
        float theta = 0.5f / (float)(i + 1);
        k_gate<<<gW, TB>>>(hcur, q_w, q_b, s);
        k_spmm<<<gW, TB>>>(hcur, h0, s, rowptr, colw, eww, sup);
        k_gemm<HID, false><<<gG, 256>>>(sup, conv_w + (size_t)i * HID * HID,
                                        nullptr, gamma, beta, theta, h);
        hcur = h;
    }

    k_cls<<<gW, TB>>>(hcur, cls_w, cls_b, out);
}

// round 2
// speedup vs baseline: 1.0769x; 1.0769x over previous
#include <cuda_runtime.h>
#include <math.h>

#define NN   100000
#define NE   1600000
#define IND  256
#define HID  128
#define NL   4
#define OUTD 7
#define LN_EPS 1e-5f
#define SCAN_NB ((NN + 1023) / 1024)   // 98

// ---------------- scratch (device globals: no allocation allowed) ----------------
__device__ float g_h0[(size_t)NN * HID];
__device__ float g_h [(size_t)NN * HID];
__device__ float g_sup[(size_t)NN * HID];
__device__ float g_s[NN];
__device__ float g_dis[NN];
__device__ int   g_cnt[NN];
__device__ int   g_cursor[NN];
__device__ int   g_rowptr[NN + 1];
__device__ int   g_colw[NE];
__device__ float g_eww[NE];
__device__ int   g_bsum[SCAN_NB + 32];
__device__ int   g_boff[SCAN_NB + 32];
__device__ float g_wmod[(size_t)NL * HID * HID];

// ---------------- graph preprocessing ----------------
__global__ void k_zero(int* cnt, int* cursor) {
    int i = blockIdx.x * blockDim.x + threadIdx.x;
    if (i < NN) { cnt[i] = 0; cursor[i] = 0; }
}

__global__ void k_hist(const int* __restrict__ row, int* __restrict__ cnt) {
    int i = blockIdx.x * blockDim.x + threadIdx.x;
    if (i < NE) atomicAdd(&cnt[row[i]], 1);
}

__global__ void k_dis(const int* __restrict__ cnt, float* __restrict__ dis) {
    int i = blockIdx.x * blockDim.x + threadIdx.x;
    if (i < NN) {
        int c = cnt[i];
        float dg = (c == 0) ? 1.0f : (float)c;
        dis[i] = rsqrtf(dg);
    }
}

// block partial sums over 1024-element chunks
__global__ void k_bsum(const int* __restrict__ cnt, int* __restrict__ bsum) {
    __shared__ int sm[256];
    const int b = blockIdx.x, t = threadIdx.x;
    int base = b * 1024;
    int s = 0;
    #pragma unroll
    for (int q = 0; q < 4; q++) {
        int i = base + q * 256 + t;
        if (i < NN) s += cnt[i];
    }
    sm[t] = s;
    __syncthreads();
    for (int off = 128; off > 0; off >>= 1) {
        if (t < off) sm[t] += sm[t + off];
        __syncthreads();
    }
    if (t == 0) bsum[b] = sm[0];
}

// exclusive scan of the (<=128) block sums
__global__ void k_bscan(const int* __restrict__ bsum, int* __restrict__ boff) {
    __shared__ int sm[128];
    int t = threadIdx.x;
    sm[t] = (t < SCAN_NB) ? bsum[t] : 0;
    __syncthreads();
    for (int off = 1; off < 128; off <<= 1) {
        int v = (t >= off) ? sm[t - off] : 0;
        __syncthreads();
        sm[t] += v;
        __syncthreads();
    }
    if (t < SCAN_NB) boff[t] = (t == 0) ? 0 : sm[t - 1];
}

// per-block exclusive scan -> rowptr
__global__ void k_rowptr(const int* __restrict__ cnt, const int* __restrict__ boff,
                         int* __restrict__ rowptr) {
    __shared__ int sm[256];
    const int b = blockIdx.x, t = threadIdx.x;
    int base = b * 1024;
    int vals[4];
    int s = 0;
    #pragma unroll
    for (int q = 0; q < 4; q++) {
        int i = base + t * 4 + q;
        vals[q] = (i < NN) ? cnt[i] : 0;
        s += vals[q];
    }
    sm[t] = s;
    __syncthreads();
    for (int off = 1; off < 256; off <<= 1) {
        int v = (t >= off) ? sm[t - off] : 0;
        __syncthreads();
        sm[t] += v;
        __syncthreads();
    }
    int run = boff[b] + ((t == 0) ? 0 : sm[t - 1]);
    #pragma unroll
    for (int q = 0; q < 4; q++) {
        int i = base + t * 4 + q;
        if (i < NN) rowptr[i] = run;
        run += vals[q];
    }
    if (b == 0 && t == 0) rowptr[NN] = NE;
}

__global__ void k_scatter(const int* __restrict__ row, const int* __restrict__ col,
                          const int* __restrict__ rowptr, int* __restrict__ cursor,
                          const float* __restrict__ dis,
                          int* __restrict__ colw, float* __restrict__ eww) {
    int i = blockIdx.x * blockDim.x + threadIdx.x;
    if (i < NE) {
        int r = row[i], c = col[i];
        int pos = rowptr[r] + atomicAdd(&cursor[r], 1);
        colw[pos] = c;
        eww[pos] = dis[r] * dis[c];
    }
}

// W'[l] = theta_l * conv_w[l] + (1-theta_l) * I
__global__ void k_prepw(const float* __restrict__ conv_w, float* __restrict__ wmod) {
    int i = blockIdx.x * blockDim.x + threadIdx.x;
    if (i < NL * HID * HID) {
        int l = i / (HID * HID);
        int rc = i - l * (HID * HID);
        int r = rc >> 7, c = rc & 127;
        float theta = 0.5f / (float)(l + 1);
        float v = theta * conv_w[i];
        if (r == c) v += 1.0f - theta;
        wmod[i] = v;
    }
}

// ---------------- SpMM + AOR blend: sup = (1-s)*A_norm@h + s*h0 ----------------
__global__ void k_spmm(const float* __restrict__ h, const float* __restrict__ h0,
                       const float* __restrict__ s, const int* __restrict__ rowptr,
                       const int* __restrict__ colw, const float* __restrict__ eww,
                       float* __restrict__ sup) {
    int wid = (blockIdx.x * blockDim.x + threadIdx.x) >> 5;
    int lane = threadIdx.x & 31;
    if (wid >= NN) return;
    int start = rowptr[wid], end = rowptr[wid + 1];
    float ax = 0.f, ay = 0.f, az = 0.f, aw = 0.f;
    for (int e0 = start; e0 < end; e0 += 32) {
        int n = end - e0; if (n > 32) n = 32;
        int c = 0; float w = 0.f;
        if (lane < n) { c = colw[e0 + lane]; w = eww[e0 + lane]; }
        for (int j = 0; j < n; j++) {
            int cj   = __shfl_sync(0xffffffffu, c, j);
            float wj = __shfl_sync(0xffffffffu, w, j);
            const float4 hv = *reinterpret_cast<const float4*>(h + (size_t)cj * HID + lane * 4);
            ax += wj * hv.x; ay += wj * hv.y; az += wj * hv.z; aw += wj * hv.w;
        }
    }
    float sr = s[wid];
    float om = 1.0f - sr;
    const float4 h0v = *reinterpret_cast<const float4*>(h0 + (size_t)wid * HID + lane * 4);
    float4 o;
    o.x = om * ax + sr * h0v.x;
    o.y = om * ay + sr * h0v.y;
    o.z = om * az + sr * h0v.z;
    o.w = om * aw + sr * h0v.w;
    *reinterpret_cast<float4*>(sup + (size_t)wid * HID + lane * 4) = o;
}

// ---------------- fused GEMM (+bias/relu) + LN + gate epilogue ----------------
// PROJ : out = LN(A @ W + bias);        s_out = sigmoid(out @ q_w + q_b - 1)
// else : out = LN(relu(A @ W'));        s_out = sigmoid(out @ q_w + q_b - 1)
// 128x128 tile, 256 threads, 8x8 microkernel, register-staged prefetch.
template<int K, bool PROJ>
__launch_bounds__(256)
__global__ void k_gemm(const float* __restrict__ A, const float* __restrict__ W,
                       const float* __restrict__ bias,
                       const float* __restrict__ gamma, const float* __restrict__ beta,
                       const float* __restrict__ qw, const float* __restrict__ qb,
                       float* __restrict__ out, float* __restrict__ s_out) {
    __shared__ float As[16][132];   // [k][row], padded for 16B alignment
    __shared__ float Bs[16][128];   // [k][col]

    const int tid = threadIdx.x;
    const int tx = tid & 15;        // col group (8 cols)
    const int ty = tid >> 4;        // row group (8 rows)
    const int r0 = blockIdx.x * 128;

    float acc[8][8];
    #pragma unroll
    for (int i = 0; i < 8; i++)
        #pragma unroll
        for (int j = 0; j < 8; j++) acc[i][j] = 0.f;

    // staging registers
    float4 areg[2], breg[2];
    // A stage: 128 rows x 4 float4 (16 k) = 512 float4, 2 per thread
    const int a_id0 = tid,      a_r0 = a_id0 >> 2, a_c0 = a_id0 & 3;
    const int a_id1 = tid + 256, a_r1 = a_id1 >> 2, a_c1 = a_id1 & 3;
    // B stage: 16 k x 32 float4 = 512 float4, 2 per thread
    const int b_id0 = tid,      b_k0 = b_id0 >> 5, b_c0 = b_id0 & 31;
    const int b_id1 = tid + 256, b_k1 = b_id1 >> 5, b_c1 = b_id1 & 31;

    auto loadA = [&](int kt) {
        areg[0] = (r0 + a_r0 < NN)
            ? *reinterpret_cast<const float4*>(A + (size_t)(r0 + a_r0) * K + kt + a_c0 * 4)
            : make_float4(0.f, 0.f, 0.f, 0.f);
        areg[1] = (r0 + a_r1 < NN)
            ? *reinterpret_cast<const float4*>(A + (size_t)(r0 + a_r1) * K + kt + a_c1 * 4)
            : make_float4(0.f, 0.f, 0.f, 0.f);
    };
    auto loadB = [&](int kt) {
        breg[0] = *reinterpret_cast<const float4*>(W + (size_t)(kt + b_k0) * HID + b_c0 * 4);
        breg[1] = *reinterpret_cast<const float4*>(W + (size_t)(kt + b_k1) * HID + b_c1 * 4);
    };

    loadA(0); loadB(0);

    for (int kt = 0; kt < K; kt += 16) {
        // commit staged tile to SMEM
        As[a_c0 * 4 + 0][a_r0] = areg[0].x;
        As[a_c0 * 4 + 1][a_r0] = areg[0].y;
        As[a_c0 * 4 + 2][a_r0] = areg[0].z;
        As[a_c0 * 4 + 3][a_r0] = areg[0].w;
        As[a_c1 * 4 + 0][a_r1] = areg[1].x;
        As[a_c1 * 4 + 1][a_r1] = areg[1].y;
        As[a_c1 * 4 + 2][a_r1] = areg[1].z;
        As[a_c1 * 4 + 3][a_r1] = areg[1].w;
        *reinterpret_cast<float4*>(&Bs[b_k0][b_c0 * 4]) = breg[0];
        *reinterpret_cast<float4*>(&Bs[b_k1][b_c1 * 4]) = breg[1];
        __syncthreads();

        if (kt + 16 < K) { loadA(kt + 16); loadB(kt + 16); }

        #pragma unroll
        for (int k = 0; k < 16; k++) {
            float4 a0 = *reinterpret_cast<const float4*>(&As[k][ty * 8]);
            float4 a1 = *reinterpret_cast<const float4*>(&As[k][ty * 8 + 4]);
            float4 b0 = *reinterpret_cast<const float4*>(&Bs[k][tx * 8]);
            float4 b1 = *reinterpret_cast<const float4*>(&Bs[k][tx * 8 + 4]);
            float av[8] = {a0.x, a0.y, a0.z, a0.w, a1.x, a1.y, a1.z, a1.w};
            float bv[8] = {b0.x, b0.y, b0.z, b0.w, b1.x, b1.y, b1.z, b1.w};
            #pragma unroll
            for (int i = 0; i < 8; i++)
                #pragma unroll
                for (int j = 0; j < 8; j++)
                    acc[i][j] += av[i] * bv[j];
        }
        __syncthreads();
    }

    // epilogue: per-row LN over 128 cols (16 threads x 8 cols) + gate
    const float4 g0  = *reinterpret_cast<const float4*>(gamma + tx * 8);
    const float4 g1  = *reinterpret_cast<const float4*>(gamma + tx * 8 + 4);
    const float4 be0 = *reinterpret_cast<const float4*>(beta  + tx * 8);
    const float4 be1 = *reinterpret_cast<const float4*>(beta  + tx * 8 + 4);
    const float4 qw0 = *reinterpret_cast<const float4*>(qw + tx * 8);
    const float4 qw1 = *reinterpret_cast<const float4*>(qw + tx * 8 + 4);
    const float qbv = qb[0];
    float4 bb0 = make_float4(0.f, 0.f, 0.f, 0.f), bb1 = bb0;
    if (PROJ) {
        bb0 = *reinterpret_cast<const float4*>(bias + tx * 8);
        bb1 = *reinterpret_cast<const float4*>(bias + tx * 8 + 4);
    }
    const float gg[8]  = {g0.x, g0.y, g0.z, g0.w, g1.x, g1.y, g1.z, g1.w};
    const float bb[8]  = {be0.x, be0.y, be0.z, be0.w, be1.x, be1.y, be1.z, be1.w};
    const float qq[8]  = {qw0.x, qw0.y, qw0.z, qw0.w, qw1.x, qw1.y, qw1.z, qw1.w};
    const float bi[8]  = {bb0.x, bb0.y, bb0.z, bb0.w, bb1.x, bb1.y, bb1.z, bb1.w};

    #pragma unroll
    for (int i = 0; i < 8; i++) {
        int r = r0 + ty * 8 + i;
        float v[8];
        #pragma unroll
        for (int j = 0; j < 8; j++) {
            if (PROJ) v[j] = acc[i][j] + bi[j];
            else      v[j] = fmaxf(acc[i][j], 0.f);
        }
        float sum = 0.f, sq = 0.f;
        #pragma unroll
        for (int j = 0; j < 8; j++) { sum += v[j]; sq += v[j] * v[j]; }
        #pragma unroll
        for (int off = 8; off > 0; off >>= 1) {
            sum += __shfl_xor_sync(0xffffffffu, sum, off);
            sq  += __shfl_xor_sync(0xffffffffu, sq,  off);
        }
        float mu  = sum * (1.0f / 128.0f);
        float var = sq * (1.0f / 128.0f) - mu * mu;
        var = fmaxf(var, 0.f);
        float rs = rsqrtf(var + LN_EPS);
        float o[8];
        float gate = 0.f;
        #pragma unroll
        for (int j = 0; j < 8; j++) {
            o[j] = gg[j] * (v[j] - mu) * rs + bb[j];
            gate += o[j] * qq[j];
        }
        #pragma unroll
        for (int off = 8; off > 0; off >>= 1)
            gate += __shfl_xor_sync(0xffffffffu, gate, off);
        if (r < NN) {
            float4 o0 = make_float4(o[0], o[1], o[2], o[3]);
            float4 o1 = make_float4(o[4], o[5], o[6], o[7]);
            *reinterpret_cast<float4*>(out + (size_t)r * HID + tx * 8)     = o0;
            *reinterpret_cast<float4*>(out + (size_t)r * HID + tx * 8 + 4) = o1;
            if (tx == 0) {
                float z = gate + qbv - 1.0f;
                s_out[r] = 1.0f / (1.0f + expf(-z));
            }
        }
    }
}

// ---------------- classifier: out = h @ cls_w + cls_b ----------------
__global__ void k_cls(const float* __restrict__ h, const float* __restrict__ cw,
                      const float* __restrict__ cb, float* __restrict__ out) {
    __shared__ float wsm[HID * OUTD];
    __shared__ float bsm[OUTD];
    for (int i = threadIdx.x; i < HID * OUTD; i += blockDim.x) wsm[i] = cw[i];
    if (threadIdx.x < OUTD) bsm[threadIdx.x] = cb[threadIdx.x];
    __syncthreads();

    int wid = (blockIdx.x * blockDim.x + threadIdx.x) >> 5;
    int lane = threadIdx.x & 31;
    if (wid >= NN) return;
    const float4 hv = *reinterpret_cast<const float4*>(h + (size_t)wid * HID + lane * 4);
    float hvv[4] = {hv.x, hv.y, hv.z, hv.w};
    float p[OUTD];
    #pragma unroll
    for (int j = 0; j < OUTD; j++) p[j] = 0.f;
    #pragma unroll
    for (int t = 0; t < 4; t++) {
        int k = lane * 4 + t;
        #pragma unroll
        for (int j = 0; j < OUTD; j++) p[j] += hvv[t] * wsm[k * OUTD + j];
    }
    #pragma unroll
    for (int off = 16; off > 0; off >>= 1)
        #pragma unroll
        for (int j = 0; j < OUTD; j++) p[j] += __shfl_xor_sync(0xffffffffu, p[j], off);
    if (lane == 0) {
        #pragma unroll
        for (int j = 0; j < OUTD; j++) out[(size_t)wid * OUTD + j] = p[j] + bsm[j];
    }
}

// ---------------- launch ----------------
extern "C" void kernel_launch(void* const* d_in, const int* in_sizes, int n_in,
                              void* d_out, int out_size) {
    const float* x      = (const float*)d_in[0];
    const int*   ei     = (const int*)d_in[1];
    const float* W_proj = (const float*)d_in[2];
    const float* b_proj = (const float*)d_in[3];
    const float* gamma  = (const float*)d_in[4];
    const float* beta   = (const float*)d_in[5];
    const float* q_w    = (const float*)d_in[6];
    const float* q_b    = (const float*)d_in[7];
    const float* conv_w = (const float*)d_in[8];
    const float* cls_w  = (const float*)d_in[9];
    const float* cls_b  = (const float*)d_in[10];
    float* out = (float*)d_out;

    const int* row = ei;
    const int* col = ei + NE;

    float *h0, *h, *sup, *s, *dis, *eww, *wmod;
    int *cnt, *cursor, *rowptr, *colw, *bsum, *boff;
    cudaGetSymbolAddress((void**)&h0, g_h0);
    cudaGetSymbolAddress((void**)&h, g_h);
    cudaGetSymbolAddress((void**)&sup, g_sup);
    cudaGetSymbolAddress((void**)&s, g_s);
    cudaGetSymbolAddress((void**)&dis, g_dis);
    cudaGetSymbolAddress((void**)&cnt, g_cnt);
    cudaGetSymbolAddress((void**)&cursor, g_cursor);
    cudaGetSymbolAddress((void**)&rowptr, g_rowptr);
    cudaGetSymbolAddress((void**)&colw, g_colw);
    cudaGetSymbolAddress((void**)&eww, g_eww);
    cudaGetSymbolAddress((void**)&bsum, g_bsum);
    cudaGetSymbolAddress((void**)&boff, g_boff);
    cudaGetSymbolAddress((void**)&wmod, g_wmod);

    const int TB = 256;
    const int gN  = (NN + TB - 1) / TB;
    const int gE  = (NE + TB - 1) / TB;
    const int gW  = (NN * 32 + TB - 1) / TB;    // warp-per-row grids
    const int gG  = (NN + 127) / 128;           // gemm grid (782)

    // graph preprocessing (CSR build)
    k_zero<<<gN, TB>>>(cnt, cursor);
    k_hist<<<gE, TB>>>(row, cnt);
    k_dis<<<gN, TB>>>(cnt, dis);
    k_bsum<<<SCAN_NB, 256>>>(cnt, bsum);
    k_bscan<<<1, 128>>>(bsum, boff);
    k_rowptr<<<SCAN_NB, 256>>>(cnt, boff, rowptr);
    k_scatter<<<gE, TB>>>(row, col, rowptr, cursor, dis, colw, eww);
    k_prepw<<<(NL * HID * HID + 255) / 256, 256>>>(conv_w, wmod);

    // h0 = LN(x @ W_proj + b_proj); s = gate(h0)
    k_gemm<IND, true><<<gG, 256>>>(x, W_proj, b_proj, gamma, beta, q_w, q_b, h0, s);

    const float* hcur = h0;
    for (int i = 0; i < NL; i++) {
        k_spmm<<<gW, TB>>>(hcur, h0, s, rowptr, colw, eww, sup);
        k_gemm<HID, false><<<gG, 256>>>(sup, wmod + (size_t)i * HID * HID,
                                        nullptr, gamma, beta, q_w, q_b, h, s);
        hcur = h;
    }

    k_cls<<<gW, TB>>>(hcur, cls_w, cls_b, out);
}

// round 9
// speedup vs baseline: 1.2403x; 1.1518x over previous
#include <cuda_runtime.h>
#include <stdint.h>
#include <math.h>

#define NN   100000
#define NE   1600000
#define IND  256
#define HID  128
#define NL   4
#define OUTD 7
#define LN_EPS 1e-5f
#define SCAN_NB ((NN + 1023) / 1024)   // 98

// ---------------- scratch (device globals: no allocation allowed) ----------------
__device__ float g_h0[(size_t)NN * HID];
__device__ float g_h [(size_t)NN * HID];
__device__ float g_sup[(size_t)NN * HID];
__device__ float g_s[NN];
__device__ float g_dis[NN];
__device__ int   g_cnt[NN];
__device__ int   g_cursor[NN];
__device__ int   g_rowptr[NN + 1];
__device__ int   g_colw[NE];
__device__ float g_eww[NE];
__device__ int   g_bsum[SCAN_NB + 32];
__device__ int   g_boff[SCAN_NB + 32];
__device__ float g_wmod[(size_t)NL * HID * HID];

// ---------------- helpers ----------------
__device__ __forceinline__ float tf32r(float x) {
    unsigned int u; asm("cvt.rna.tf32.f32 %0, %1;" : "=r"(u) : "f"(x));
    return __uint_as_float(u);
}

__device__ __forceinline__ void mma_tf32(float* d, const unsigned int* a, const unsigned int* b) {
    asm volatile(
        "mma.sync.aligned.m16n8k8.row.col.f32.tf32.tf32.f32 "
        "{%0,%1,%2,%3}, {%4,%5,%6,%7}, {%8,%9}, {%0,%1,%2,%3};\n"
        : "+f"(d[0]), "+f"(d[1]), "+f"(d[2]), "+f"(d[3])
        : "r"(a[0]), "r"(a[1]), "r"(a[2]), "r"(a[3]), "r"(b[0]), "r"(b[1]));
}

__device__ __forceinline__ void cp_async16(unsigned int smem_addr, const void* gptr, int src_sz) {
    asm volatile("cp.async.cg.shared.global [%0], [%1], 16, %2;\n"
                 :: "r"(smem_addr), "l"(gptr), "r"(src_sz));
}

// ---------------- graph preprocessing ----------------
__global__ void k_zero(int* cnt, int* cursor) {
    int i = blockIdx.x * blockDim.x + threadIdx.x;
    if (i < NN) { cnt[i] = 0; cursor[i] = 0; }
}

__global__ void k_hist(const int* __restrict__ row, int* __restrict__ cnt) {
    int i = blockIdx.x * blockDim.x + threadIdx.x;
    if (i < NE) atomicAdd(&cnt[row[i]], 1);
}

__global__ void k_dis(const int* __restrict__ cnt, float* __restrict__ dis) {
    int i = blockIdx.x * blockDim.x + threadIdx.x;
    if (i < NN) {
        int c = cnt[i];
        float dg = (c == 0) ? 1.0f : (float)c;
        dis[i] = rsqrtf(dg);
    }
}

__global__ void k_bsum(const int* __restrict__ cnt, int* __restrict__ bsum) {
    __shared__ int sm[256];
    const int b = blockIdx.x, t = threadIdx.x;
    int base = b * 1024;
    int s = 0;
    #pragma unroll
    for (int q = 0; q < 4; q++) {
        int i = base + q * 256 + t;
        if (i < NN) s += cnt[i];
    }
    sm[t] = s;
    __syncthreads();
    for (int off = 128; off > 0; off >>= 1) {
        if (t < off) sm[t] += sm[t + off];
        __syncthreads();
    }
    if (t == 0) bsum[b] = sm[0];
}

__global__ void k_bscan(const int* __restrict__ bsum, int* __restrict__ boff) {
    __shared__ int sm[128];
    int t = threadIdx.x;
    sm[t] = (t < SCAN_NB) ? bsum[t] : 0;
    __syncthreads();
    for (int off = 1; off < 128; off <<= 1) {
        int v = (t >= off) ? sm[t - off] : 0;
        __syncthreads();
        sm[t] += v;
        __syncthreads();
    }
    if (t < SCAN_NB) boff[t] = (t == 0) ? 0 : sm[t - 1];
}

__global__ void k_rowptr(const int* __restrict__ cnt, const int* __restrict__ boff,
                         int* __restrict__ rowptr) {
    __shared__ int sm[256];
    const int b = blockIdx.x, t = threadIdx.x;
    int base = b * 1024;
    int vals[4];
    int s = 0;
    #pragma unroll
    for (int q = 0; q < 4; q++) {
        int i = base + t * 4 + q;
        vals[q] = (i < NN) ? cnt[i] : 0;
        s += vals[q];
    }
    sm[t] = s;
    __syncthreads();
    for (int off = 1; off < 256; off <<= 1) {
        int v = (t >= off) ? sm[t - off] : 0;
        __syncthreads();
        sm[t] += v;
        __syncthreads();
    }
    int run = boff[b] + ((t == 0) ? 0 : sm[t - 1]);
    #pragma unroll
    for (int q = 0; q < 4; q++) {
        int i = base + t * 4 + q;
        if (i < NN) rowptr[i] = run;
        run += vals[q];
    }
    if (b == 0 && t == 0) rowptr[NN] = NE;
}

__global__ void k_scatter(const int* __restrict__ row, const int* __restrict__ col,
                          const int* __restrict__ rowptr, int* __restrict__ cursor,
                          const float* __restrict__ dis,
                          int* __restrict__ colw, float* __restrict__ eww) {
    int i = blockIdx.x * blockDim.x + threadIdx.x;
    if (i < NE) {
        int r = row[i], c = col[i];
        int pos = rowptr[r] + atomicAdd(&cursor[r], 1);
        colw[pos] = c;
        eww[pos] = dis[r] * dis[c];
    }
}

// W'[l] = theta_l * conv_w[l] + (1-theta_l) * I   (full fp32; split happens in GEMM)
__global__ void k_prepw(const float* __restrict__ conv_w, float* __restrict__ wmod) {
    int i = blockIdx.x * blockDim.x + threadIdx.x;
    if (i < NL * HID * HID) {
        int l = i / (HID * HID);
        int rc = i - l * (HID * HID);
        int r = rc >> 7, c = rc & 127;
        float theta = 0.5f / (float)(l + 1);
        float v = theta * conv_w[i];
        if (r == c) v += 1.0f - theta;
        wmod[i] = v;
    }
}

// ---------------- SpMM + AOR blend (full fp32) ----------------
__global__ void k_spmm(const float* __restrict__ h, const float* __restrict__ h0,
                       const float* __restrict__ s, const int* __restrict__ rowptr,
                       const int* __restrict__ colw, const float* __restrict__ eww,
                       float* __restrict__ sup) {
    int wid = (blockIdx.x * blockDim.x + threadIdx.x) >> 5;
    int lane = threadIdx.x & 31;
    if (wid >= NN) return;
    int start = rowptr[wid], end = rowptr[wid + 1];
    float ax = 0.f, ay = 0.f, az = 0.f, aw = 0.f;
    for (int e0 = start; e0 < end; e0 += 32) {
        int n = end - e0; if (n > 32) n = 32;
        int c = 0; float w = 0.f;
        if (lane < n) { c = colw[e0 + lane]; w = eww[e0 + lane]; }
        for (int j = 0; j < n; j++) {
            int cj   = __shfl_sync(0xffffffffu, c, j);
            float wj = __shfl_sync(0xffffffffu, w, j);
            const float4 hv = *reinterpret_cast<const float4*>(h + (size_t)cj * HID + lane * 4);
            ax += wj * hv.x; ay += wj * hv.y; az += wj * hv.z; aw += wj * hv.w;
        }
    }
    float sr = s[wid];
    float om = 1.0f - sr;
    const float4 h0v = *reinterpret_cast<const float4*>(h0 + (size_t)wid * HID + lane * 4);
    float4 o;
    o.x = om * ax + sr * h0v.x;
    o.y = om * ay + sr * h0v.y;
    o.z = om * az + sr * h0v.z;
    o.w = om * aw + sr * h0v.w;
    *reinterpret_cast<float4*>(sup + (size_t)wid * HID + lane * 4) = o;
}

// ---------------- 3xTF32 tensor-core GEMM + LN + gate epilogue ----------------
// PROJ : out = LN(A @ W + bias);   else : out = LN(relu(A @ W'))
// s_out = sigmoid(out @ q_w + q_b - 1)
// Split precision: v = hi + lo (both tf32); A·B ≈ Ah·Bh + Ah·Bl + Al·Bh.
template<int K, bool PROJ>
__launch_bounds__(256)
__global__ void k_gemm_tc(const float* __restrict__ A, const float* __restrict__ W,
                          const float* __restrict__ bias,
                          const float* __restrict__ gamma, const float* __restrict__ beta,
                          const float* __restrict__ qw, const float* __restrict__ qb,
                          float* __restrict__ out, float* __restrict__ s_out) {
    constexpr int KC = 16;
    constexpr int NK = K / KC;
    constexpr int AP = 20;    // As row pitch (conflict-free)
    constexpr int BP = 136;   // Bs k-row pitch (conflict-free)

    __shared__ float As[2][128 * AP];
    __shared__ float Bs[2][KC * BP];
    __shared__ float st_sum[2][128], st_sq[2][128], st_g[2][128];
    __shared__ float gsm[128], besm[128], qsm[128], bism[128];

    const int tid = threadIdx.x;
    const int lane = tid & 31;
    const int warp = tid >> 5;
    const int wm = warp & 3;          // rows wm*32
    const int wn = warp >> 2;         // cols wn*64
    const int g  = lane >> 2;
    const int t  = lane & 3;
    const int r0 = blockIdx.x * 128;
    const float qbv = qb[0];

    if (tid < 128) {
        gsm[tid]  = gamma[tid];
        besm[tid] = beta[tid];
        qsm[tid]  = qw[tid];
        bism[tid] = PROJ ? bias[tid] : 0.f;
    }

    // cp.async tiling: A 128x16 floats -> 512 16B chunks (2/thread)
    const int ar = tid >> 2, ac = tid & 3;
    // B 16x128 floats -> 512 16B chunks (2/thread)
    const int bk = tid >> 5, bc = tid & 31;

    auto issue = [&](int kt, int buf) {
        {
            unsigned int d0 = (unsigned int)__cvta_generic_to_shared(&As[buf][ar * AP + ac * 4]);
            cp_async16(d0, A + (size_t)(r0 + ar) * K + kt + ac * 4, (r0 + ar < NN) ? 16 : 0);
            unsigned int d1 = (unsigned int)__cvta_generic_to_shared(&As[buf][(ar + 64) * AP + ac * 4]);
            cp_async16(d1, A + (size_t)(r0 + ar + 64) * K + kt + ac * 4, (r0 + ar + 64 < NN) ? 16 : 0);
        }
        {
            unsigned int d0 = (unsigned int)__cvta_generic_to_shared(&Bs[buf][bk * BP + bc * 4]);
            cp_async16(d0, W + (size_t)(kt + bk) * HID + bc * 4, 16);
            unsigned int d1 = (unsigned int)__cvta_generic_to_shared(&Bs[buf][(bk + 8) * BP + bc * 4]);
            cp_async16(d1, W + (size_t)(kt + bk + 8) * HID + bc * 4, 16);
        }
        asm volatile("cp.async.commit_group;\n");
    };

    float acc[2][8][4];
    #pragma unroll
    for (int mt = 0; mt < 2; mt++)
        #pragma unroll
        for (int nt = 0; nt < 8; nt++)
            #pragma unroll
            for (int q = 0; q < 4; q++) acc[mt][nt][q] = 0.f;

    issue(0, 0);

    #pragma unroll
    for (int i = 0; i < NK; i++) {
        if (i + 1 < NK) {
            issue((i + 1) * KC, (i + 1) & 1);
            asm volatile("cp.async.wait_group 1;\n");
        } else {
            asm volatile("cp.async.wait_group 0;\n");
        }
        __syncthreads();
        const float* as = As[i & 1];
        const float* bs = Bs[i & 1];
        #pragma unroll
        for (int ks = 0; ks < KC / 8; ks++) {
            unsigned int afh[2][4], afl[2][4];
            #pragma unroll
            for (int mt = 0; mt < 2; mt++) {
                int rb = wm * 32 + mt * 16;
                float v0 = as[(rb + g)     * AP + ks * 8 + t];
                float v1 = as[(rb + g + 8) * AP + ks * 8 + t];
                float v2 = as[(rb + g)     * AP + ks * 8 + t + 4];
                float v3 = as[(rb + g + 8) * AP + ks * 8 + t + 4];
                float h0v = tf32r(v0), h1v = tf32r(v1), h2v = tf32r(v2), h3v = tf32r(v3);
                afh[mt][0] = __float_as_uint(h0v);
                afh[mt][1] = __float_as_uint(h1v);
                afh[mt][2] = __float_as_uint(h2v);
                afh[mt][3] = __float_as_uint(h3v);
                afl[mt][0] = __float_as_uint(tf32r(v0 - h0v));
                afl[mt][1] = __float_as_uint(tf32r(v1 - h1v));
                afl[mt][2] = __float_as_uint(tf32r(v2 - h2v));
                afl[mt][3] = __float_as_uint(tf32r(v3 - h3v));
            }
            unsigned int bfh[8][2], bfl[8][2];
            #pragma unroll
            for (int nt = 0; nt < 8; nt++) {
                int cb = wn * 64 + nt * 8 + g;
                float v0 = bs[(ks * 8 + t)     * BP + cb];
                float v1 = bs[(ks * 8 + t + 4) * BP + cb];
                float h0v = tf32r(v0), h1v = tf32r(v1);
                bfh[nt][0] = __float_as_uint(h0v);
                bfh[nt][1] = __float_as_uint(h1v);
                bfl[nt][0] = __float_as_uint(tf32r(v0 - h0v));
                bfl[nt][1] = __float_as_uint(tf32r(v1 - h1v));
            }
            #pragma unroll
            for (int mt = 0; mt < 2; mt++)
                #pragma unroll
                for (int nt = 0; nt < 8; nt++) {
                    mma_tf32(acc[mt][nt], afh[mt], bfl[nt]);   // hi*lo
                    mma_tf32(acc[mt][nt], afl[mt], bfh[nt]);   // lo*hi
                    mma_tf32(acc[mt][nt], afh[mt], bfh[nt]);   // hi*hi (largest last)
                }
        }
        __syncthreads();
    }

    // ---- epilogue in fragment layout ----
    float vsum[2][2], vsq[2][2];
    #pragma unroll
    for (int mt = 0; mt < 2; mt++)
        #pragma unroll
        for (int hf = 0; hf < 2; hf++) { vsum[mt][hf] = 0.f; vsq[mt][hf] = 0.f; }

    #pragma unroll
    for (int mt = 0; mt < 2; mt++)
        #pragma unroll
        for (int nt = 0; nt < 8; nt++) {
            int c0 = wn * 64 + nt * 8 + 2 * t;
            #pragma unroll
            for (int q = 0; q < 4; q++) {
                int col = c0 + (q & 1);
                float v = acc[mt][nt][q];
                v = PROJ ? (v + bism[col]) : fmaxf(v, 0.f);
                acc[mt][nt][q] = v;
                int hf = q >> 1;
                vsum[mt][hf] += v;
                vsq[mt][hf]  += v * v;
            }
        }

    #pragma unroll
    for (int off = 1; off <= 2; off <<= 1)
        #pragma unroll
        for (int mt = 0; mt < 2; mt++)
            #pragma unroll
            for (int hf = 0; hf < 2; hf++) {
                vsum[mt][hf] += __shfl_xor_sync(0xffffffffu, vsum[mt][hf], off);
                vsq[mt][hf]  += __shfl_xor_sync(0xffffffffu, vsq[mt][hf],  off);
            }

    if (t == 0) {
        #pragma unroll
        for (int mt = 0; mt < 2; mt++)
            #pragma unroll
            for (int hf = 0; hf < 2; hf++) {
                int rl = wm * 32 + mt * 16 + g + hf * 8;
                st_sum[wn][rl] = vsum[mt][hf];
                st_sq[wn][rl]  = vsq[mt][hf];
            }
    }
    __syncthreads();

    float mu[2][2], rs[2][2];
    #pragma unroll
    for (int mt = 0; mt < 2; mt++)
        #pragma unroll
        for (int hf = 0; hf < 2; hf++) {
            int rl = wm * 32 + mt * 16 + g + hf * 8;
            float sm = st_sum[0][rl] + st_sum[1][rl];
            float sq = st_sq[0][rl]  + st_sq[1][rl];
            float m = sm * (1.0f / 128.0f);
            float var = sq * (1.0f / 128.0f) - m * m;
            var = fmaxf(var, 0.f);
            mu[mt][hf] = m;
            rs[mt][hf] = rsqrtf(var + LN_EPS);
        }

    float gp[2][2];
    #pragma unroll
    for (int mt = 0; mt < 2; mt++)
        #pragma unroll
        for (int hf = 0; hf < 2; hf++) gp[mt][hf] = 0.f;

    #pragma unroll
    for (int mt = 0; mt < 2; mt++)
        #pragma unroll
        for (int nt = 0; nt < 8; nt++) {
            int c0 = wn * 64 + nt * 8 + 2 * t;
            #pragma unroll
            for (int hf = 0; hf < 2; hf++) {
                float o0 = gsm[c0]     * (acc[mt][nt][hf * 2 + 0] - mu[mt][hf]) * rs[mt][hf] + besm[c0];
                float o1 = gsm[c0 + 1] * (acc[mt][nt][hf * 2 + 1] - mu[mt][hf]) * rs[mt][hf] + besm[c0 + 1];
                gp[mt][hf] += o0 * qsm[c0] + o1 * qsm[c0 + 1];
                int r = r0 + wm * 32 + mt * 16 + g + hf * 8;
                if (r < NN) {
                    float2 o2 = make_float2(o0, o1);
                    *reinterpret_cast<float2*>(out + (size_t)r * HID + c0) = o2;
                }
            }
        }

    #pragma unroll
    for (int off = 1; off <= 2; off <<= 1)
        #pragma unroll
        for (int mt = 0; mt < 2; mt++)
            #pragma unroll
            for (int hf = 0; hf < 2; hf++)
                gp[mt][hf] += __shfl_xor_sync(0xffffffffu, gp[mt][hf], off);

    if (t == 0) {
        #pragma unroll
        for (int mt = 0; mt < 2; mt++)
            #pragma unroll
            for (int hf = 0; hf < 2; hf++) {
                int rl = wm * 32 + mt * 16 + g + hf * 8;
                st_g[wn][rl] = gp[mt][hf];
            }
    }
    __syncthreads();

    if (wn == 0 && t == 0) {
        #pragma unroll
        for (int mt = 0; mt < 2; mt++)
            #pragma unroll
            for (int hf = 0; hf < 2; hf++) {
                int rl = wm * 32 + mt * 16 + g + hf * 8;
                int r = r0 + rl;
                if (r < NN) {
                    float z = st_g[0][rl] + st_g[1][rl] + qbv - 1.0f;
                    s_out[r] = 1.0f / (1.0f + expf(-z));
                }
            }
    }
}

// ---------------- classifier: out = h @ cls_w + cls_b ----------------
__global__ void k_cls(const float* __restrict__ h, const float* __restrict__ cw,
                      const float* __restrict__ cb, float* __restrict__ out) {
    __shared__ float wsm[HID * OUTD];
    __shared__ float bsm[OUTD];
    for (int i = threadIdx.x; i < HID * OUTD; i += blockDim.x) wsm[i] = cw[i];
    if (threadIdx.x < OUTD) bsm[threadIdx.x] = cb[threadIdx.x];
    __syncthreads();

    int wid = (blockIdx.x * blockDim.x + threadIdx.x) >> 5;
    int lane = threadIdx.x & 31;
    if (wid >= NN) return;
    const float4 hv = *reinterpret_cast<const float4*>(h + (size_t)wid * HID + lane * 4);
    float hvv[4] = {hv.x, hv.y, hv.z, hv.w};
    float p[OUTD];
    #pragma unroll
    for (int j = 0; j < OUTD; j++) p[j] = 0.f;
    #pragma unroll
    for (int tq = 0; tq < 4; tq++) {
        int k = lane * 4 + tq;
        #pragma unroll
        for (int j = 0; j < OUTD; j++) p[j] += hvv[tq] * wsm[k * OUTD + j];
    }
    #pragma unroll
    for (int off = 16; off > 0; off >>= 1)
        #pragma unroll
        for (int j = 0; j < OUTD; j++) p[j] += __shfl_xor_sync(0xffffffffu, p[j], off);
    if (lane == 0) {
        #pragma unroll
        for (int j = 0; j < OUTD; j++) out[(size_t)wid * OUTD + j] = p[j] + bsm[j];
    }
}

// ---------------- launch ----------------
extern "C" void kernel_launch(void* const* d_in, const int* in_sizes, int n_in,
                              void* d_out, int out_size) {
    const float* x      = (const float*)d_in[0];
    const int*   ei     = (const int*)d_in[1];
    const float* W_proj = (const float*)d_in[2];
    const float* b_proj = (const float*)d_in[3];
    const float* gamma  = (const float*)d_in[4];
    const float* beta   = (const float*)d_in[5];
    const float* q_w    = (const float*)d_in[6];
    const float* q_b    = (const float*)d_in[7];
    const float* conv_w = (const float*)d_in[8];
    const float* cls_w  = (const float*)d_in[9];
    const float* cls_b  = (const float*)d_in[10];
    float* out = (float*)d_out;

    const int* row = ei;
    const int* col = ei + NE;

    float *h0, *h, *sup, *s, *dis, *eww, *wmod;
    int *cnt, *cursor, *rowptr, *colw, *bsum, *boff;
    cudaGetSymbolAddress((void**)&h0, g_h0);
    cudaGetSymbolAddress((void**)&h, g_h);
    cudaGetSymbolAddress((void**)&sup, g_sup);
    cudaGetSymbolAddress((void**)&s, g_s);
    cudaGetSymbolAddress((void**)&dis, g_dis);
    cudaGetSymbolAddress((void**)&cnt, g_cnt);
    cudaGetSymbolAddress((void**)&cursor, g_cursor);
    cudaGetSymbolAddress((void**)&rowptr, g_rowptr);
    cudaGetSymbolAddress((void**)&colw, g_colw);
    cudaGetSymbolAddress((void**)&eww, g_eww);
    cudaGetSymbolAddress((void**)&bsum, g_bsum);
    cudaGetSymbolAddress((void**)&boff, g_boff);
    cudaGetSymbolAddress((void**)&wmod, g_wmod);

    const int TB = 256;
    const int gN  = (NN + TB - 1) / TB;
    const int gE  = (NE + TB - 1) / TB;
    const int gW  = (NN * 32 + TB - 1) / TB;    // warp-per-row grids
    const int gG  = (NN + 127) / 128;           // gemm grid (782)

    // graph preprocessing (CSR build) + weight prep
    k_zero<<<gN, TB>>>(cnt, cursor);
    k_hist<<<gE, TB>>>(row, cnt);
    k_dis<<<gN, TB>>>(cnt, dis);
    k_bsum<<<SCAN_NB, 256>>>(cnt, bsum);
    k_bscan<<<1, 128>>>(bsum, boff);
    k_rowptr<<<SCAN_NB, 256>>>(cnt, boff, rowptr);
    k_scatter<<<gE, TB>>>(row, col, rowptr, cursor, dis, colw, eww);
    k_prepw<<<(NL * HID * HID + 255) / 256, 256>>>(conv_w, wmod);

    // h0 = LN(x @ W_proj + b_proj); s = gate(h0)
    k_gemm_tc<IND, true><<<gG, 256>>>(x, W_proj, b_proj, gamma, beta, q_w, q_b, h0, s);

    const float* hcur = h0;
    for (int i = 0; i < NL; i++) {
        k_spmm<<<gW, TB>>>(hcur, h0, s, rowptr, colw, eww, sup);
        k_gemm_tc<HID, false><<<gG, 256>>>(sup, wmod + (size_t)i * HID * HID,
                                           nullptr, gamma, beta, q_w, q_b, h, s);
        hcur = h;
    }

    k_cls<<<gW, TB>>>(hcur, cls_w, cls_b, out);
}

// round 10
// speedup vs baseline: 1.2822x; 1.0338x over previous
#include <cuda_runtime.h>
#include <stdint.h>
#include <math.h>

#define NN   100000
#define NE   1600000
#define IND  256
#define HID  128
#define NL   4
#define OUTD 7
#define LN_EPS 1e-5f
#define SCAN_NB ((NN + 1023) / 1024)   // 98

// ---------------- scratch (device globals: no allocation allowed) ----------------
__device__ float g_h0[(size_t)NN * HID];
__device__ float g_h [(size_t)NN * HID];
__device__ float g_suph[(size_t)NN * HID];
__device__ float g_supl[(size_t)NN * HID];
__device__ float g_s[NN];
__device__ float g_dis[NN];
__device__ int   g_cnt[NN];
__device__ int   g_cursor[NN];
__device__ int   g_rowptr[NN + 1];
__device__ int   g_colw[NE];
__device__ float g_eww[NE];
__device__ int   g_bsum[SCAN_NB + 32];
__device__ int   g_boff[SCAN_NB + 32];
__device__ float g_wmodh[(size_t)NL * HID * HID];
__device__ float g_wmodl[(size_t)NL * HID * HID];
__device__ float g_wprojh[(size_t)IND * HID];
__device__ float g_wprojl[(size_t)IND * HID];

// ---------------- helpers ----------------
__device__ __forceinline__ float tf32r(float x) {
    unsigned int u; asm("cvt.rna.tf32.f32 %0, %1;" : "=r"(u) : "f"(x));
    return __uint_as_float(u);
}

__device__ __forceinline__ void mma_tf32(float* d, const unsigned int* a, const unsigned int* b) {
    asm volatile(
        "mma.sync.aligned.m16n8k8.row.col.f32.tf32.tf32.f32 "
        "{%0,%1,%2,%3}, {%4,%5,%6,%7}, {%8,%9}, {%0,%1,%2,%3};\n"
        : "+f"(d[0]), "+f"(d[1]), "+f"(d[2]), "+f"(d[3])
        : "r"(a[0]), "r"(a[1]), "r"(a[2]), "r"(a[3]), "r"(b[0]), "r"(b[1]));
}

__device__ __forceinline__ void cp_async16(unsigned int smem_addr, const void* gptr, int src_sz) {
    asm volatile("cp.async.cg.shared.global [%0], [%1], 16, %2;\n"
                 :: "r"(smem_addr), "l"(gptr), "r"(src_sz));
}

// ---------------- graph preprocessing ----------------
__global__ void k_zero(int* cnt, int* cursor) {
    int i = blockIdx.x * blockDim.x + threadIdx.x;
    if (i < NN) { cnt[i] = 0; cursor[i] = 0; }
}

__global__ void k_hist(const int* __restrict__ row, int* __restrict__ cnt) {
    int i = blockIdx.x * blockDim.x + threadIdx.x;
    if (i < NE) atomicAdd(&cnt[row[i]], 1);
}

__global__ void k_dis(const int* __restrict__ cnt, float* __restrict__ dis) {
    int i = blockIdx.x * blockDim.x + threadIdx.x;
    if (i < NN) {
        int c = cnt[i];
        float dg = (c == 0) ? 1.0f : (float)c;
        dis[i] = rsqrtf(dg);
    }
}

__global__ void k_bsum(const int* __restrict__ cnt, int* __restrict__ bsum) {
    __shared__ int sm[256];
    const int b = blockIdx.x, t = threadIdx.x;
    int base = b * 1024;
    int s = 0;
    #pragma unroll
    for (int q = 0; q < 4; q++) {
        int i = base + q * 256 + t;
        if (i < NN) s += cnt[i];
    }
    sm[t] = s;
    __syncthreads();
    for (int off = 128; off > 0; off >>= 1) {
        if (t < off) sm[t] += sm[t + off];
        __syncthreads();
    }
    if (t == 0) bsum[b] = sm[0];
}

__global__ void k_bscan(const int* __restrict__ bsum, int* __restrict__ boff) {
    __shared__ int sm[128];
    int t = threadIdx.x;
    sm[t] = (t < SCAN_NB) ? bsum[t] : 0;
    __syncthreads();
    for (int off = 1; off < 128; off <<= 1) {
        int v = (t >= off) ? sm[t - off] : 0;
        __syncthreads();
        sm[t] += v;
        __syncthreads();
    }
    if (t < SCAN_NB) boff[t] = (t == 0) ? 0 : sm[t - 1];
}

__global__ void k_rowptr(const int* __restrict__ cnt, const int* __restrict__ boff,
                         int* __restrict__ rowptr) {
    __shared__ int sm[256];
    const int b = blockIdx.x, t = threadIdx.x;
    int base = b * 1024;
    int vals[4];
    int s = 0;
    #pragma unroll
    for (int q = 0; q < 4; q++) {
        int i = base + t * 4 + q;
        vals[q] = (i < NN) ? cnt[i] : 0;
        s += vals[q];
    }
    sm[t] = s;
    __syncthreads();
    for (int off = 1; off < 256; off <<= 1) {
        int v = (t >= off) ? sm[t - off] : 0;
        __syncthreads();
        sm[t] += v;
        __syncthreads();
    }
    int run = boff[b] + ((t == 0) ? 0 : sm[t - 1]);
    #pragma unroll
    for (int q = 0; q < 4; q++) {
        int i = base + t * 4 + q;
        if (i < NN) rowptr[i] = run;
        run += vals[q];
    }
    if (b == 0 && t == 0) rowptr[NN] = NE;
}

__global__ void k_scatter(const int* __restrict__ row, const int* __restrict__ col,
                          const int* __restrict__ rowptr, int* __restrict__ cursor,
                          const float* __restrict__ dis,
                          int* __restrict__ colw, float* __restrict__ eww) {
    int i = blockIdx.x * blockDim.x + threadIdx.x;
    if (i < NE) {
        int r = row[i], c = col[i];
        int pos = rowptr[r] + atomicAdd(&cursor[r], 1);
        colw[pos] = c;
        eww[pos] = dis[r] * dis[c];
    }
}

// W'[l] = theta_l*conv_w[l] + (1-theta_l)*I, pre-split into tf32 hi/lo planes
__global__ void k_prepw(const float* __restrict__ conv_w,
                        float* __restrict__ wh, float* __restrict__ wl) {
    int i = blockIdx.x * blockDim.x + threadIdx.x;
    if (i < NL * HID * HID) {
        int l = i / (HID * HID);
        int rc = i - l * (HID * HID);
        int r = rc >> 7, c = rc & 127;
        float theta = 0.5f / (float)(l + 1);
        float v = theta * conv_w[i];
        if (r == c) v += 1.0f - theta;
        float hi = tf32r(v);
        wh[i] = hi;
        wl[i] = tf32r(v - hi);
    }
}

__global__ void k_prepproj(const float* __restrict__ wp,
                           float* __restrict__ wh, float* __restrict__ wl) {
    int i = blockIdx.x * blockDim.x + threadIdx.x;
    if (i < IND * HID) {
        float v = wp[i];
        float hi = tf32r(v);
        wh[i] = hi;
        wl[i] = tf32r(v - hi);
    }
}

// ---------------- SpMM + AOR blend, output pre-split into hi/lo planes ----------------
__global__ void k_spmm(const float* __restrict__ h, const float* __restrict__ h0,
                       const float* __restrict__ s, const int* __restrict__ rowptr,
                       const int* __restrict__ colw, const float* __restrict__ eww,
                       float* __restrict__ suph, float* __restrict__ supl) {
    int wid = (blockIdx.x * blockDim.x + threadIdx.x) >> 5;
    int lane = threadIdx.x & 31;
    if (wid >= NN) return;
    int start = rowptr[wid], end = rowptr[wid + 1];
    float ax = 0.f, ay = 0.f, az = 0.f, aw = 0.f;
    for (int e0 = start; e0 < end; e0 += 32) {
        int n = end - e0; if (n > 32) n = 32;
        int c = 0; float w = 0.f;
        if (lane < n) { c = colw[e0 + lane]; w = eww[e0 + lane]; }
        for (int j = 0; j < n; j++) {
            int cj   = __shfl_sync(0xffffffffu, c, j);
            float wj = __shfl_sync(0xffffffffu, w, j);
            const float4 hv = *reinterpret_cast<const float4*>(h + (size_t)cj * HID + lane * 4);
            ax += wj * hv.x; ay += wj * hv.y; az += wj * hv.z; aw += wj * hv.w;
        }
    }
    float sr = s[wid];
    float om = 1.0f - sr;
    const float4 h0v = *reinterpret_cast<const float4*>(h0 + (size_t)wid * HID + lane * 4);
    float vx = om * ax + sr * h0v.x;
    float vy = om * ay + sr * h0v.y;
    float vz = om * az + sr * h0v.z;
    float vw = om * aw + sr * h0v.w;
    float4 hi, lo;
    hi.x = tf32r(vx); lo.x = tf32r(vx - hi.x);
    hi.y = tf32r(vy); lo.y = tf32r(vy - hi.y);
    hi.z = tf32r(vz); lo.z = tf32r(vz - hi.z);
    hi.w = tf32r(vw); lo.w = tf32r(vw - hi.w);
    *reinterpret_cast<float4*>(suph + (size_t)wid * HID + lane * 4) = hi;
    *reinterpret_cast<float4*>(supl + (size_t)wid * HID + lane * 4) = lo;
}

// ---------------- 3xTF32 tensor-core GEMM + LN + gate epilogue ----------------
// PROJ : out = LN(A @ W + bias)  (A fp32, split at fragment load)
// else : out = LN(relu(A @ W')) (A pre-split hi/lo planes)
// s_out = sigmoid(out @ q_w + q_b - 1)
// W always pre-split (Wh, Wl). A·B = Ah·Bh + Ah·Bl + Al·Bh.
#define AP 20     // As row pitch (floats, conflict-free)
#define BP 136    // Bs k-row pitch (floats, conflict-free)
#define KC 16
// dynamic smem layout (floats)
#define O_ASH 0                      // 2 * 128*AP = 5120
#define O_ASL 5120                   // 2 * 128*AP = 5120
#define O_BSH 10240                  // 2 * KC*BP  = 4352
#define O_BSL 14592                  // 2 * KC*BP  = 4352
#define O_STS 18944                  // 256
#define O_STQ 19200                  // 256
#define O_STG 19456                  // 256
#define O_PAR 19712                  // 512 (gamma,beta,qw,bias)
#define SMEM_FLOATS 20224
#define SMEM_BYTES (SMEM_FLOATS * 4)

template<int K, bool PROJ>
__launch_bounds__(256)
__global__ void k_gemm_tc(const float* __restrict__ Ah, const float* __restrict__ Al,
                          const float* __restrict__ Wh, const float* __restrict__ Wl,
                          const float* __restrict__ bias,
                          const float* __restrict__ gamma, const float* __restrict__ beta,
                          const float* __restrict__ qw, const float* __restrict__ qb,
                          float* __restrict__ out, float* __restrict__ s_out) {
    constexpr int NK = K / KC;
    extern __shared__ float smx[];
    float* Ash = smx + O_ASH;
    float* Asl = smx + O_ASL;
    float* Bsh = smx + O_BSH;
    float* Bsl = smx + O_BSL;
    float* stS = smx + O_STS;
    float* stQ = smx + O_STQ;
    float* stG = smx + O_STG;
    float* gsm = smx + O_PAR;
    float* besm = gsm + 128;
    float* qsm  = gsm + 256;
    float* bism = gsm + 384;

    const int tid = threadIdx.x;
    const int lane = tid & 31;
    const int warp = tid >> 5;
    const int wm = warp & 3;          // rows wm*32
    const int wn = warp >> 2;         // cols wn*64
    const int g  = lane >> 2;
    const int t  = lane & 3;
    const int r0 = blockIdx.x * 128;
    const float qbv = qb[0];

    if (tid < 128) {
        gsm[tid]  = gamma[tid];
        besm[tid] = beta[tid];
        qsm[tid]  = qw[tid];
        bism[tid] = PROJ ? bias[tid] : 0.f;
    }

    // cp.async tiling: A 128x16 floats -> 512 16B chunks (2/thread/plane)
    const int ar = tid >> 2, ac = tid & 3;
    // B 16x128 floats -> 512 16B chunks (2/thread/plane)
    const int bk = tid >> 5, bc = tid & 31;

    auto issue = [&](int kt, int buf) {
        const int ab = buf * (128 * AP);
        const int bb = buf * (KC * BP);
        int sz0 = (r0 + ar < NN) ? 16 : 0;
        int sz1 = (r0 + ar + 64 < NN) ? 16 : 0;
        {
            unsigned int d0 = (unsigned int)__cvta_generic_to_shared(&Ash[ab + ar * AP + ac * 4]);
            cp_async16(d0, Ah + (size_t)(r0 + ar) * K + kt + ac * 4, sz0);
            unsigned int d1 = (unsigned int)__cvta_generic_to_shared(&Ash[ab + (ar + 64) * AP + ac * 4]);
            cp_async16(d1, Ah + (size_t)(r0 + ar + 64) * K + kt + ac * 4, sz1);
        }
        if (!PROJ) {
            unsigned int d0 = (unsigned int)__cvta_generic_to_shared(&Asl[ab + ar * AP + ac * 4]);
            cp_async16(d0, Al + (size_t)(r0 + ar) * K + kt + ac * 4, sz0);
            unsigned int d1 = (unsigned int)__cvta_generic_to_shared(&Asl[ab + (ar + 64) * AP + ac * 4]);
            cp_async16(d1, Al + (size_t)(r0 + ar + 64) * K + kt + ac * 4, sz1);
        }
        {
            unsigned int d0 = (unsigned int)__cvta_generic_to_shared(&Bsh[bb + bk * BP + bc * 4]);
            cp_async16(d0, Wh + (size_t)(kt + bk) * HID + bc * 4, 16);
            unsigned int d1 = (unsigned int)__cvta_generic_to_shared(&Bsh[bb + (bk + 8) * BP + bc * 4]);
            cp_async16(d1, Wh + (size_t)(kt + bk + 8) * HID + bc * 4, 16);
        }
        {
            unsigned int d0 = (unsigned int)__cvta_generic_to_shared(&Bsl[bb + bk * BP + bc * 4]);
            cp_async16(d0, Wl + (size_t)(kt + bk) * HID + bc * 4, 16);
            unsigned int d1 = (unsigned int)__cvta_generic_to_shared(&Bsl[bb + (bk + 8) * BP + bc * 4]);
            cp_async16(d1, Wl + (size_t)(kt + bk + 8) * HID + bc * 4, 16);
        }
        asm volatile("cp.async.commit_group;\n");
    };

    float acc[2][8][4];
    #pragma unroll
    for (int mt = 0; mt < 2; mt++)
        #pragma unroll
        for (int nt = 0; nt < 8; nt++)
            #pragma unroll
            for (int q = 0; q < 4; q++) acc[mt][nt][q] = 0.f;

    issue(0, 0);

    #pragma unroll
    for (int i = 0; i < NK; i++) {
        if (i + 1 < NK) {
            issue((i + 1) * KC, (i + 1) & 1);
            asm volatile("cp.async.wait_group 1;\n");
        } else {
            asm volatile("cp.async.wait_group 0;\n");
        }
        __syncthreads();
        const int ab = (i & 1) * (128 * AP);
        const int bb = (i & 1) * (KC * BP);
        const float* ash = Ash + ab;
        const float* asl = Asl + ab;
        const float* bsh = Bsh + bb;
        const float* bsl = Bsl + bb;
        #pragma unroll
        for (int ks = 0; ks < KC / 8; ks++) {
            unsigned int afh[2][4], afl[2][4];
            #pragma unroll
            for (int mt = 0; mt < 2; mt++) {
                int rb = wm * 32 + mt * 16;
                if (PROJ) {
                    float v0 = ash[(rb + g)     * AP + ks * 8 + t];
                    float v1 = ash[(rb + g + 8) * AP + ks * 8 + t];
                    float v2 = ash[(rb + g)     * AP + ks * 8 + t + 4];
                    float v3 = ash[(rb + g + 8) * AP + ks * 8 + t + 4];
                    float h0v = tf32r(v0), h1v = tf32r(v1), h2v = tf32r(v2), h3v = tf32r(v3);
                    afh[mt][0] = __float_as_uint(h0v);
                    afh[mt][1] = __float_as_uint(h1v);
                    afh[mt][2] = __float_as_uint(h2v);
                    afh[mt][3] = __float_as_uint(h3v);
                    afl[mt][0] = __float_as_uint(tf32r(v0 - h0v));
                    afl[mt][1] = __float_as_uint(tf32r(v1 - h1v));
                    afl[mt][2] = __float_as_uint(tf32r(v2 - h2v));
                    afl[mt][3] = __float_as_uint(tf32r(v3 - h3v));
                } else {
                    afh[mt][0] = __float_as_uint(ash[(rb + g)     * AP + ks * 8 + t]);
                    afh[mt][1] = __float_as_uint(ash[(rb + g + 8) * AP + ks * 8 + t]);
                    afh[mt][2] = __float_as_uint(ash[(rb + g)     * AP + ks * 8 + t + 4]);
                    afh[mt][3] = __float_as_uint(ash[(rb + g + 8) * AP + ks * 8 + t + 4]);
                    afl[mt][0] = __float_as_uint(asl[(rb + g)     * AP + ks * 8 + t]);
                    afl[mt][1] = __float_as_uint(asl[(rb + g + 8) * AP + ks * 8 + t]);
                    afl[mt][2] = __float_as_uint(asl[(rb + g)     * AP + ks * 8 + t + 4]);
                    afl[mt][3] = __float_as_uint(asl[(rb + g + 8) * AP + ks * 8 + t + 4]);
                }
            }
            unsigned int bfh[8][2], bfl[8][2];
            #pragma unroll
            for (int nt = 0; nt < 8; nt++) {
                int cb = wn * 64 + nt * 8 + g;
                bfh[nt][0] = __float_as_uint(bsh[(ks * 8 + t)     * BP + cb]);
                bfh[nt][1] = __float_as_uint(bsh[(ks * 8 + t + 4) * BP + cb]);
                bfl[nt][0] = __float_as_uint(bsl[(ks * 8 + t)     * BP + cb]);
                bfl[nt][1] = __float_as_uint(bsl[(ks * 8 + t + 4) * BP + cb]);
            }
            #pragma unroll
            for (int mt = 0; mt < 2; mt++)
                #pragma unroll
                for (int nt = 0; nt < 8; nt++) {
                    mma_tf32(acc[mt][nt], afh[mt], bfl[nt]);   // hi*lo
                    mma_tf32(acc[mt][nt], afl[mt], bfh[nt]);   // lo*hi
                    mma_tf32(acc[mt][nt], afh[mt], bfh[nt]);   // hi*hi (largest last)
                }
        }
        __syncthreads();
    }

    // ---- epilogue in fragment layout ----
    float vsum[2][2], vsq[2][2];
    #pragma unroll
    for (int mt = 0; mt < 2; mt++)
        #pragma unroll
        for (int hf = 0; hf < 2; hf++) { vsum[mt][hf] = 0.f; vsq[mt][hf] = 0.f; }

    #pragma unroll
    for (int mt = 0; mt < 2; mt++)
        #pragma unroll
        for (int nt = 0; nt < 8; nt++) {
            int c0 = wn * 64 + nt * 8 + 2 * t;
            #pragma unroll
            for (int q = 0; q < 4; q++) {
                int col = c0 + (q & 1);
                float v = acc[mt][nt][q];
                v = PROJ ? (v + bism[col]) : fmaxf(v, 0.f);
                acc[mt][nt][q] = v;
                int hf = q >> 1;
                vsum[mt][hf] += v;
                vsq[mt][hf]  += v * v;
            }
        }

    #pragma unroll
    for (int off = 1; off <= 2; off <<= 1)
        #pragma unroll
        for (int mt = 0; mt < 2; mt++)
            #pragma unroll
            for (int hf = 0; hf < 2; hf++) {
                vsum[mt][hf] += __shfl_xor_sync(0xffffffffu, vsum[mt][hf], off);
                vsq[mt][hf]  += __shfl_xor_sync(0xffffffffu, vsq[mt][hf],  off);
            }

    if (t == 0) {
        #pragma unroll
        for (int mt = 0; mt < 2; mt++)
            #pragma unroll
            for (int hf = 0; hf < 2; hf++) {
                int rl = wm * 32 + mt * 16 + g + hf * 8;
                stS[wn * 128 + rl] = vsum[mt][hf];
                stQ[wn * 128 + rl] = vsq[mt][hf];
            }
    }
    __syncthreads();

    float mu[2][2], rs[2][2];
    #pragma unroll
    for (int mt = 0; mt < 2; mt++)
        #pragma unroll
        for (int hf = 0; hf < 2; hf++) {
            int rl = wm * 32 + mt * 16 + g + hf * 8;
            float sm = stS[rl] + stS[128 + rl];
            float sq = stQ[rl] + stQ[128 + rl];
            float m = sm * (1.0f / 128.0f);
            float var = sq * (1.0f / 128.0f) - m * m;
            var = fmaxf(var, 0.f);
            mu[mt][hf] = m;
            rs[mt][hf] = rsqrtf(var + LN_EPS);
        }

    float gp[2][2];
    #pragma unroll
    for (int mt = 0; mt < 2; mt++)
        #pragma unroll
        for (int hf = 0; hf < 2; hf++) gp[mt][hf] = 0.f;

    #pragma unroll
    for (int mt = 0; mt < 2; mt++)
        #pragma unroll
        for (int nt = 0; nt < 8; nt++) {
            int c0 = wn * 64 + nt * 8 + 2 * t;
            #pragma unroll
            for (int hf = 0; hf < 2; hf++) {
                float o0 = gsm[c0]     * (acc[mt][nt][hf * 2 + 0] - mu[mt][hf]) * rs[mt][hf] + besm[c0];
                float o1 = gsm[c0 + 1] * (acc[mt][nt][hf * 2 + 1] - mu[mt][hf]) * rs[mt][hf] + besm[c0 + 1];
                gp[mt][hf] += o0 * qsm[c0] + o1 * qsm[c0 + 1];
                int r = r0 + wm * 32 + mt * 16 + g + hf * 8;
                if (r < NN) {
                    float2 o2 = make_float2(o0, o1);
                    *reinterpret_cast<float2*>(out + (size_t)r * HID + c0) = o2;
                }
            }
        }

    #pragma unroll
    for (int off = 1; off <= 2; off <<= 1)
        #pragma unroll
        for (int mt = 0; mt < 2; mt++)
            #pragma unroll
            for (int hf = 0; hf < 2; hf++)
                gp[mt][hf] += __shfl_xor_sync(0xffffffffu, gp[mt][hf], off);

    if (t == 0) {
        #pragma unroll
        for (int mt = 0; mt < 2; mt++)
            #pragma unroll
            for (int hf = 0; hf < 2; hf++) {
                int rl = wm * 32 + mt * 16 + g + hf * 8;
                stG[wn * 128 + rl] = gp[mt][hf];
            }
    }
    __syncthreads();

    if (wn == 0 && t == 0) {
        #pragma unroll
        for (int mt = 0; mt < 2; mt++)
            #pragma unroll
            for (int hf = 0; hf < 2; hf++) {
                int rl = wm * 32 + mt * 16 + g + hf * 8;
                int r = r0 + rl;
                if (r < NN) {
                    float z = stG[rl] + stG[128 + rl] + qbv - 1.0f;
                    s_out[r] = 1.0f / (1.0f + expf(-z));
                }
            }
    }
}

// ---------------- classifier: out = h @ cls_w + cls_b ----------------
__global__ void k_cls(const float* __restrict__ h, const float* __restrict__ cw,
                      const float* __restrict__ cb, float* __restrict__ out) {
    __shared__ float wsm[HID * OUTD];
    __shared__ float bsm[OUTD];
    for (int i = threadIdx.x; i < HID * OUTD; i += blockDim.x) wsm[i] = cw[i];
    if (threadIdx.x < OUTD) bsm[threadIdx.x] = cb[threadIdx.x];
    __syncthreads();

    int wid = (blockIdx.x * blockDim.x + threadIdx.x) >> 5;
    int lane = threadIdx.x & 31;
    if (wid >= NN) return;
    const float4 hv = *reinterpret_cast<const float4*>(h + (size_t)wid * HID + lane * 4);
    float hvv[4] = {hv.x, hv.y, hv.z, hv.w};
    float p[OUTD];
    #pragma unroll
    for (int j = 0; j < OUTD; j++) p[j] = 0.f;
    #pragma unroll
    for (int tq = 0; tq < 4; tq++) {
        int k = lane * 4 + tq;
        #pragma unroll
        for (int j = 0; j < OUTD; j++) p[j] += hvv[tq] * wsm[k * OUTD + j];
    }
    #pragma unroll
    for (int off = 16; off > 0; off >>= 1)
        #pragma unroll
        for (int j = 0; j < OUTD; j++) p[j] += __shfl_xor_sync(0xffffffffu, p[j], off);
    if (lane == 0) {
        #pragma unroll
        for (int j = 0; j < OUTD; j++) out[(size_t)wid * OUTD + j] = p[j] + bsm[j];
    }
}

// ---------------- launch ----------------
extern "C" void kernel_launch(void* const* d_in, const int* in_sizes, int n_in,
                              void* d_out, int out_size) {
    const float* x      = (const float*)d_in[0];
    const int*   ei     = (const int*)d_in[1];
    const float* W_proj = (const float*)d_in[2];
    const float* b_proj = (const float*)d_in[3];
    const float* gamma  = (const float*)d_in[4];
    const float* beta   = (const float*)d_in[5];
    const float* q_w    = (const float*)d_in[6];
    const float* q_b    = (const float*)d_in[7];
    const float* conv_w = (const float*)d_in[8];
    const float* cls_w  = (const float*)d_in[9];
    const float* cls_b  = (const float*)d_in[10];
    float* out = (float*)d_out;

    const int* row = ei;
    const int* col = ei + NE;

    float *h0, *h, *suph, *supl, *s, *dis, *eww, *wmh, *wml, *wph, *wpl;
    int *cnt, *cursor, *rowptr, *colw, *bsum, *boff;
    cudaGetSymbolAddress((void**)&h0, g_h0);
    cudaGetSymbolAddress((void**)&h, g_h);
    cudaGetSymbolAddress((void**)&suph, g_suph);
    cudaGetSymbolAddress((void**)&supl, g_supl);
    cudaGetSymbolAddress((void**)&s, g_s);
    cudaGetSymbolAddress((void**)&dis, g_dis);
    cudaGetSymbolAddress((void**)&cnt, g_cnt);
    cudaGetSymbolAddress((void**)&cursor, g_cursor);
    cudaGetSymbolAddress((void**)&rowptr, g_rowptr);
    cudaGetSymbolAddress((void**)&colw, g_colw);
    cudaGetSymbolAddress((void**)&eww, g_eww);
    cudaGetSymbolAddress((void**)&bsum, g_bsum);
    cudaGetSymbolAddress((void**)&boff, g_boff);
    cudaGetSymbolAddress((void**)&wmh, g_wmodh);
    cudaGetSymbolAddress((void**)&wml, g_wmodl);
    cudaGetSymbolAddress((void**)&wph, g_wprojh);
    cudaGetSymbolAddress((void**)&wpl, g_wprojl);

    // opt into >48KB dynamic smem (host-side attribute set; idempotent)
    static_assert(SMEM_BYTES <= 100 * 1024, "smem");
    cudaFuncSetAttribute(k_gemm_tc<IND, true>,
                         cudaFuncAttributeMaxDynamicSharedMemorySize, SMEM_BYTES);
    cudaFuncSetAttribute(k_gemm_tc<HID, false>,
                         cudaFuncAttributeMaxDynamicSharedMemorySize, SMEM_BYTES);

    const int TB = 256;
    const int gN  = (NN + TB - 1) / TB;
    const int gE  = (NE + TB - 1) / TB;
    const int gW  = (NN * 32 + TB - 1) / TB;    // warp-per-row grids
    const int gG  = (NN + 127) / 128;           // gemm grid (782)

    // graph preprocessing (CSR build) + weight prep
    k_zero<<<gN, TB>>>(cnt, cursor);
    k_hist<<<gE, TB>>>(row, cnt);
    k_dis<<<gN, TB>>>(cnt, dis);
    k_bsum<<<SCAN_NB, 256>>>(cnt, bsum);
    k_bscan<<<1, 128>>>(bsum, boff);
    k_rowptr<<<SCAN_NB, 256>>>(cnt, boff, rowptr);
    k_scatter<<<gE, TB>>>(row, col, rowptr, cursor, dis, colw, eww);
    k_prepw<<<(NL * HID * HID + 255) / 256, 256>>>(conv_w, wmh, wml);
    k_prepproj<<<(IND * HID + 255) / 256, 256>>>(W_proj, wph, wpl);

    // h0 = LN(x @ W_proj + b_proj); s = gate(h0)
    k_gemm_tc<IND, true><<<gG, 256, SMEM_BYTES>>>(x, nullptr, wph, wpl, b_proj,
                                                  gamma, beta, q_w, q_b, h0, s);

    const float* hcur = h0;
    for (int i = 0; i < NL; i++) {
        k_spmm<<<gW, TB>>>(hcur, h0, s, rowptr, colw, eww, suph, supl);
        k_gemm_tc<HID, false><<<gG, 256, SMEM_BYTES>>>(suph, supl,
                                                       wmh + (size_t)i * HID * HID,
                                                       wml + (size_t)i * HID * HID,
                                                       nullptr, gamma, beta, q_w, q_b, h, s);
        hcur = h;
    }

    k_cls<<<gW, TB>>>(hcur, cls_w, cls_b, out);
}

// round 11
// speedup vs baseline: 1.5751x; 1.2284x over previous
#include <cuda_runtime.h>
#include <cuda_bf16.h>
#include <stdint.h>
#include <math.h>

#define NN   100000
#define NE   1600000
#define IND  256
#define HID  128
#define NL   4
#define OUTD 7
#define LN_EPS 1e-5f
#define SCAN_NB ((NN + 1023) / 1024)   // 98

// ---------------- scratch (device globals: no allocation allowed) ----------------
__device__ float g_h0[(size_t)NN * HID];
__device__ float g_h [(size_t)NN * HID];
__device__ __nv_bfloat16 g_suph[(size_t)NN * HID];
__device__ __nv_bfloat16 g_supl[(size_t)NN * HID];
__device__ __nv_bfloat16 g_xh[(size_t)NN * IND];
__device__ __nv_bfloat16 g_xl[(size_t)NN * IND];
__device__ float g_s[NN];
__device__ float g_dis[NN];
__device__ int   g_cnt[NN];
__device__ int   g_cursor[NN];
__device__ int   g_rowptr[NN + 1];
__device__ int   g_colw[NE];
__device__ float g_eww[NE];
__device__ int   g_bsum[SCAN_NB + 32];
__device__ int   g_boff[SCAN_NB + 32];
__device__ __nv_bfloat16 g_wmodh[(size_t)NL * HID * HID];   // [l][n][k]
__device__ __nv_bfloat16 g_wmodl[(size_t)NL * HID * HID];
__device__ __nv_bfloat16 g_wprojh[(size_t)HID * IND];       // [n][k]
__device__ __nv_bfloat16 g_wprojl[(size_t)HID * IND];

// ---------------- helpers ----------------
__device__ __forceinline__ void bf16split(float v, __nv_bfloat16& hi, __nv_bfloat16& lo) {
    hi = __float2bfloat16(v);
    lo = __float2bfloat16(v - __bfloat162float(hi));
}

__device__ __forceinline__ void mma_bf16(float* d, const unsigned int* a, const unsigned int* b) {
    asm volatile(
        "mma.sync.aligned.m16n8k16.row.col.f32.bf16.bf16.f32 "
        "{%0,%1,%2,%3}, {%4,%5,%6,%7}, {%8,%9}, {%0,%1,%2,%3};\n"
        : "+f"(d[0]), "+f"(d[1]), "+f"(d[2]), "+f"(d[3])
        : "r"(a[0]), "r"(a[1]), "r"(a[2]), "r"(a[3]), "r"(b[0]), "r"(b[1]));
}

__device__ __forceinline__ void cp_async16(unsigned int smem_addr, const void* gptr, int src_sz) {
    asm volatile("cp.async.cg.shared.global [%0], [%1], 16, %2;\n"
                 :: "r"(smem_addr), "l"(gptr), "r"(src_sz));
}

// ---------------- input pre-split kernels ----------------
// x -> bf16 hi/lo planes (row-major [row][k], 4 elems/thread)
__global__ void k_prepx(const float* __restrict__ x,
                        __nv_bfloat16* __restrict__ xh, __nv_bfloat16* __restrict__ xl) {
    size_t i4 = (size_t)(blockIdx.x * blockDim.x + threadIdx.x);
    if (i4 >= ((size_t)NN * IND) / 4) return;
    const float4 v = *reinterpret_cast<const float4*>(x + i4 * 4);
    __nv_bfloat16 h0, h1, h2, h3, l0, l1, l2, l3;
    bf16split(v.x, h0, l0); bf16split(v.y, h1, l1);
    bf16split(v.z, h2, l2); bf16split(v.w, h3, l3);
    __nv_bfloat162 hp0 = __halves2bfloat162(h0, h1), hp1 = __halves2bfloat162(h2, h3);
    __nv_bfloat162 lp0 = __halves2bfloat162(l0, l1), lp1 = __halves2bfloat162(l2, l3);
    uint2 ho, lo2;
    ho.x = *reinterpret_cast<unsigned int*>(&hp0); ho.y = *reinterpret_cast<unsigned int*>(&hp1);
    lo2.x = *reinterpret_cast<unsigned int*>(&lp0); lo2.y = *reinterpret_cast<unsigned int*>(&lp1);
    *reinterpret_cast<uint2*>(xh + i4 * 4) = ho;
    *reinterpret_cast<uint2*>(xl + i4 * 4) = lo2;
}

// W_proj [k][n] -> transposed bf16 planes [n][k]
__global__ void k_prepproj(const float* __restrict__ wp,
                           __nv_bfloat16* __restrict__ wh, __nv_bfloat16* __restrict__ wl) {
    int i = blockIdx.x * blockDim.x + threadIdx.x;
    if (i < IND * HID) {
        int n = i / IND, k = i - n * IND;
        float v = wp[(size_t)k * HID + n];
        __nv_bfloat16 hi, lo;
        bf16split(v, hi, lo);
        wh[i] = hi; wl[i] = lo;
    }
}

// W'[l] = theta_l*conv_w[l] + (1-theta_l)*I, transposed bf16 planes [l][n][k]
__global__ void k_prepw(const float* __restrict__ conv_w,
                        __nv_bfloat16* __restrict__ wh, __nv_bfloat16* __restrict__ wl) {
    int i = blockIdx.x * blockDim.x + threadIdx.x;
    if (i < NL * HID * HID) {
        int l = i / (HID * HID);
        int rc = i - l * (HID * HID);
        int n = rc >> 7, k = rc & 127;
        float theta = 0.5f / (float)(l + 1);
        float v = theta * conv_w[(size_t)l * HID * HID + k * HID + n];
        if (k == n) v += 1.0f - theta;
        __nv_bfloat16 hi, lo;
        bf16split(v, hi, lo);
        wh[i] = hi; wl[i] = lo;
    }
}

// ---------------- graph preprocessing ----------------
__global__ void k_zero(int* cnt, int* cursor) {
    int i = blockIdx.x * blockDim.x + threadIdx.x;
    if (i < NN) { cnt[i] = 0; cursor[i] = 0; }
}

__global__ void k_hist(const int* __restrict__ row, int* __restrict__ cnt) {
    int i = blockIdx.x * blockDim.x + threadIdx.x;
    if (i < NE) atomicAdd(&cnt[row[i]], 1);
}

__global__ void k_dis(const int* __restrict__ cnt, float* __restrict__ dis) {
    int i = blockIdx.x * blockDim.x + threadIdx.x;
    if (i < NN) {
        int c = cnt[i];
        float dg = (c == 0) ? 1.0f : (float)c;
        dis[i] = rsqrtf(dg);
    }
}

__global__ void k_bsum(const int* __restrict__ cnt, int* __restrict__ bsum) {
    __shared__ int sm[256];
    const int b = blockIdx.x, t = threadIdx.x;
    int base = b * 1024;
    int s = 0;
    #pragma unroll
    for (int q = 0; q < 4; q++) {
        int i = base + q * 256 + t;
        if (i < NN) s += cnt[i];
    }
    sm[t] = s;
    __syncthreads();
    for (int off = 128; off > 0; off >>= 1) {
        if (t < off) sm[t] += sm[t + off];
        __syncthreads();
    }
    if (t == 0) bsum[b] = sm[0];
}

__global__ void k_bscan(const int* __restrict__ bsum, int* __restrict__ boff) {
    __shared__ int sm[128];
    int t = threadIdx.x;
    sm[t] = (t < SCAN_NB) ? bsum[t] : 0;
    __syncthreads();
    for (int off = 1; off < 128; off <<= 1) {
        int v = (t >= off) ? sm[t - off] : 0;
        __syncthreads();
        sm[t] += v;
        __syncthreads();
    }
    if (t < SCAN_NB) boff[t] = (t == 0) ? 0 : sm[t - 1];
}

__global__ void k_rowptr(const int* __restrict__ cnt, const int* __restrict__ boff,
                         int* __restrict__ rowptr) {
    __shared__ int sm[256];
    const int b = blockIdx.x, t = threadIdx.x;
    int base = b * 1024;
    int vals[4];
    int s = 0;
    #pragma unroll
    for (int q = 0; q < 4; q++) {
        int i = base + t * 4 + q;
        vals[q] = (i < NN) ? cnt[i] : 0;
        s += vals[q];
    }
    sm[t] = s;
    __syncthreads();
    for (int off = 1; off < 256; off <<= 1) {
        int v = (t >= off) ? sm[t - off] : 0;
        __syncthreads();
        sm[t] += v;
        __syncthreads();
    }
    int run = boff[b] + ((t == 0) ? 0 : sm[t - 1]);
    #pragma unroll
    for (int q = 0; q < 4; q++) {
        int i = base + t * 4 + q;
        if (i < NN) rowptr[i] = run;
        run += vals[q];
    }
    if (b == 0 && t == 0) rowptr[NN] = NE;
}

__global__ void k_scatter(const int* __restrict__ row, const int* __restrict__ col,
                          const int* __restrict__ rowptr, int* __restrict__ cursor,
                          const float* __restrict__ dis,
                          int* __restrict__ colw, float* __restrict__ eww) {
    int i = blockIdx.x * blockDim.x + threadIdx.x;
    if (i < NE) {
        int r = row[i], c = col[i];
        int pos = rowptr[r] + atomicAdd(&cursor[r], 1);
        colw[pos] = c;
        eww[pos] = dis[r] * dis[c];
    }
}

// ---------------- SpMM + AOR blend, output pre-split into bf16 hi/lo planes ----------------
__global__ void k_spmm(const float* __restrict__ h, const float* __restrict__ h0,
                       const float* __restrict__ s, const int* __restrict__ rowptr,
                       const int* __restrict__ colw, const float* __restrict__ eww,
                       __nv_bfloat16* __restrict__ suph, __nv_bfloat16* __restrict__ supl) {
    int wid = (blockIdx.x * blockDim.x + threadIdx.x) >> 5;
    int lane = threadIdx.x & 31;
    if (wid >= NN) return;
    int start = rowptr[wid], end = rowptr[wid + 1];
    float ax = 0.f, ay = 0.f, az = 0.f, aw = 0.f;
    for (int e0 = start; e0 < end; e0 += 32) {
        int n = end - e0; if (n > 32) n = 32;
        int c = 0; float w = 0.f;
        if (lane < n) { c = colw[e0 + lane]; w = eww[e0 + lane]; }
        for (int j = 0; j < n; j++) {
            int cj   = __shfl_sync(0xffffffffu, c, j);
            float wj = __shfl_sync(0xffffffffu, w, j);
            const float4 hv = *reinterpret_cast<const float4*>(h + (size_t)cj * HID + lane * 4);
            ax += wj * hv.x; ay += wj * hv.y; az += wj * hv.z; aw += wj * hv.w;
        }
    }
    float sr = s[wid];
    float om = 1.0f - sr;
    const float4 h0v = *reinterpret_cast<const float4*>(h0 + (size_t)wid * HID + lane * 4);
    float vx = om * ax + sr * h0v.x;
    float vy = om * ay + sr * h0v.y;
    float vz = om * az + sr * h0v.z;
    float vw = om * aw + sr * h0v.w;
    __nv_bfloat16 hx, lx, hy, ly, hz, lz, hw, lw;
    bf16split(vx, hx, lx); bf16split(vy, hy, ly);
    bf16split(vz, hz, lz); bf16split(vw, hw, lw);
    __nv_bfloat162 hp0 = __halves2bfloat162(hx, hy), hp1 = __halves2bfloat162(hz, hw);
    __nv_bfloat162 lp0 = __halves2bfloat162(lx, ly), lp1 = __halves2bfloat162(lz, lw);
    uint2 ho, lo2;
    ho.x = *reinterpret_cast<unsigned int*>(&hp0); ho.y = *reinterpret_cast<unsigned int*>(&hp1);
    lo2.x = *reinterpret_cast<unsigned int*>(&lp0); lo2.y = *reinterpret_cast<unsigned int*>(&lp1);
    *reinterpret_cast<uint2*>(suph + (size_t)wid * HID + lane * 4) = ho;
    *reinterpret_cast<uint2*>(supl + (size_t)wid * HID + lane * 4) = lo2;
}

// ---------------- 3xBF16 tensor-core GEMM (m16n8k16) + LN + gate epilogue ----------------
// PROJ : out = LN(A @ W + bias);  else : out = LN(relu(A @ W'))
// s_out = sigmoid(out @ q_w + q_b - 1)
// All operands pre-split bf16 planes. A [row][k]; W transposed [n][k].
// A·B = Ah·Bh + Ah·Bl + Al·Bh (al·bl ~2^-18 dropped).
#define KC 16                 // K per chunk = one m16n8k16
#define PITCH 24              // bf16 row pitch (12 words: g*12+t distinct mod 32)
#define PLANE_B (128 * PITCH * 2)       // 6144 bytes per plane-buffer
#define O_AH 0
#define O_AL (2 * PLANE_B)
#define O_BH (4 * PLANE_B)
#define O_BL (6 * PLANE_B)
#define O_FLT (8 * PLANE_B)             // 49152: float region
#define SMEM_BYTES (O_FLT + (256 * 3 + 512) * 4)   // 54272

template<int K, bool PROJ>
__launch_bounds__(256)
__global__ void k_gemm_tc(const __nv_bfloat16* __restrict__ Ah, const __nv_bfloat16* __restrict__ Al,
                          const __nv_bfloat16* __restrict__ Wh, const __nv_bfloat16* __restrict__ Wl,
                          const float* __restrict__ bias,
                          const float* __restrict__ gamma, const float* __restrict__ beta,
                          const float* __restrict__ qw, const float* __restrict__ qb,
                          float* __restrict__ out, float* __restrict__ s_out) {
    constexpr int NK = K / KC;
    extern __shared__ char smc[];
    float* fl  = (float*)(smc + O_FLT);
    float* stS = fl;
    float* stQ = fl + 256;
    float* stG = fl + 512;
    float* gsm = fl + 768;
    float* besm = gsm + 128;
    float* qsm  = gsm + 256;
    float* bism = gsm + 384;

    const int tid = threadIdx.x;
    const int lane = tid & 31;
    const int warp = tid >> 5;
    const int wm = warp & 3;          // rows wm*32
    const int wn = warp >> 2;         // cols wn*64
    const int g  = lane >> 2;
    const int t  = lane & 3;
    const int r0 = blockIdx.x * 128;
    const float qbv = qb[0];

    if (tid < 128) {
        gsm[tid]  = gamma[tid];
        besm[tid] = beta[tid];
        qsm[tid]  = qw[tid];
        bism[tid] = PROJ ? bias[tid] : 0.f;
    }

    // cp.async: per plane 128 rows x 2 16B-chunks; 1 op/thread/plane
    const int crow = tid >> 1, chalf = tid & 1;

    auto issue = [&](int kt, int buf) {
        const int dof = crow * (PITCH * 2) + chalf * 16;   // dest byte offset in plane
        const int soff = kt + chalf * 8;                   // src element offset
        int szA = (r0 + crow < NN) ? 16 : 0;
        unsigned int d;
        d = (unsigned int)__cvta_generic_to_shared(smc + O_AH + buf * PLANE_B + dof);
        cp_async16(d, Ah + (size_t)(r0 + crow) * K + soff, szA);
        d = (unsigned int)__cvta_generic_to_shared(smc + O_AL + buf * PLANE_B + dof);
        cp_async16(d, Al + (size_t)(r0 + crow) * K + soff, szA);
        d = (unsigned int)__cvta_generic_to_shared(smc + O_BH + buf * PLANE_B + dof);
        cp_async16(d, Wh + (size_t)crow * K + soff, 16);
        d = (unsigned int)__cvta_generic_to_shared(smc + O_BL + buf * PLANE_B + dof);
        cp_async16(d, Wl + (size_t)crow * K + soff, 16);
        asm volatile("cp.async.commit_group;\n");
    };

    float acc[2][8][4];
    #pragma unroll
    for (int mt = 0; mt < 2; mt++)
        #pragma unroll
        for (int nt = 0; nt < 8; nt++)
            #pragma unroll
            for (int q = 0; q < 4; q++) acc[mt][nt][q] = 0.f;

    issue(0, 0);

    #pragma unroll
    for (int i = 0; i < NK; i++) {
        if (i + 1 < NK) {
            issue((i + 1) * KC, (i + 1) & 1);
            asm volatile("cp.async.wait_group 1;\n");
        } else {
            asm volatile("cp.async.wait_group 0;\n");
        }
        __syncthreads();
        const int bo = (i & 1) * PLANE_B;
        const __nv_bfloat16* ash = (const __nv_bfloat16*)(smc + O_AH + bo);
        const __nv_bfloat16* asl = (const __nv_bfloat16*)(smc + O_AL + bo);
        const __nv_bfloat16* bsh = (const __nv_bfloat16*)(smc + O_BH + bo);
        const __nv_bfloat16* bsl = (const __nv_bfloat16*)(smc + O_BL + bo);

        unsigned int afh[2][4], afl[2][4];
        #pragma unroll
        for (int mt = 0; mt < 2; mt++) {
            const int r1 = (wm * 32 + mt * 16 + g) * PITCH;
            const int r2 = r1 + 8 * PITCH;
            afh[mt][0] = *(const unsigned int*)&ash[r1 + 2 * t];
            afh[mt][1] = *(const unsigned int*)&ash[r2 + 2 * t];
            afh[mt][2] = *(const unsigned int*)&ash[r1 + 8 + 2 * t];
            afh[mt][3] = *(const unsigned int*)&ash[r2 + 8 + 2 * t];
            afl[mt][0] = *(const unsigned int*)&asl[r1 + 2 * t];
            afl[mt][1] = *(const unsigned int*)&asl[r2 + 2 * t];
            afl[mt][2] = *(const unsigned int*)&asl[r1 + 8 + 2 * t];
            afl[mt][3] = *(const unsigned int*)&asl[r2 + 8 + 2 * t];
        }
        unsigned int bfh[8][2], bfl[8][2];
        #pragma unroll
        for (int nt = 0; nt < 8; nt++) {
            const int nb = (wn * 64 + nt * 8 + g) * PITCH;
            bfh[nt][0] = *(const unsigned int*)&bsh[nb + 2 * t];
            bfh[nt][1] = *(const unsigned int*)&bsh[nb + 8 + 2 * t];
            bfl[nt][0] = *(const unsigned int*)&bsl[nb + 2 * t];
            bfl[nt][1] = *(const unsigned int*)&bsl[nb + 8 + 2 * t];
        }
        #pragma unroll
        for (int mt = 0; mt < 2; mt++)
            #pragma unroll
            for (int nt = 0; nt < 8; nt++) {
                mma_bf16(acc[mt][nt], afh[mt], bfl[nt]);   // hi*lo
                mma_bf16(acc[mt][nt], afl[mt], bfh[nt]);   // lo*hi
                mma_bf16(acc[mt][nt], afh[mt], bfh[nt]);   // hi*hi (largest last)
            }
        __syncthreads();
    }

    // ---- epilogue in fragment layout (same m16n8 C layout) ----
    float vsum[2][2], vsq[2][2];
    #pragma unroll
    for (int mt = 0; mt < 2; mt++)
        #pragma unroll
        for (int hf = 0; hf < 2; hf++) { vsum[mt][hf] = 0.f; vsq[mt][hf] = 0.f; }

    #pragma unroll
    for (int mt = 0; mt < 2; mt++)
        #pragma unroll
        for (int nt = 0; nt < 8; nt++) {
            int c0 = wn * 64 + nt * 8 + 2 * t;
            #pragma unroll
            for (int q = 0; q < 4; q++) {
                int col = c0 + (q & 1);
                float v = acc[mt][nt][q];
                v = PROJ ? (v + bism[col]) : fmaxf(v, 0.f);
                acc[mt][nt][q] = v;
                int hf = q >> 1;
                vsum[mt][hf] += v;
                vsq[mt][hf]  += v * v;
            }
        }

    #pragma unroll
    for (int off = 1; off <= 2; off <<= 1)
        #pragma unroll
        for (int mt = 0; mt < 2; mt++)
            #pragma unroll
            for (int hf = 0; hf < 2; hf++) {
                vsum[mt][hf] += __shfl_xor_sync(0xffffffffu, vsum[mt][hf], off);
                vsq[mt][hf]  += __shfl_xor_sync(0xffffffffu, vsq[mt][hf],  off);
            }

    if (t == 0) {
        #pragma unroll
        for (int mt = 0; mt < 2; mt++)
            #pragma unroll
            for (int hf = 0; hf < 2; hf++) {
                int rl = wm * 32 + mt * 16 + g + hf * 8;
                stS[wn * 128 + rl] = vsum[mt][hf];
                stQ[wn * 128 + rl] = vsq[mt][hf];
            }
    }
    __syncthreads();

    float mu[2][2], rs[2][2];
    #pragma unroll
    for (int mt = 0; mt < 2; mt++)
        #pragma unroll
        for (int hf = 0; hf < 2; hf++) {
            int rl = wm * 32 + mt * 16 + g + hf * 8;
            float sm = stS[rl] + stS[128 + rl];
            float sq = stQ[rl] + stQ[128 + rl];
            float m = sm * (1.0f / 128.0f);
            float var = sq * (1.0f / 128.0f) - m * m;
            var = fmaxf(var, 0.f);
            mu[mt][hf] = m;
            rs[mt][hf] = rsqrtf(var + LN_EPS);
        }

    float gp[2][2];
    #pragma unroll
    for (int mt = 0; mt < 2; mt++)
        #pragma unroll
        for (int hf = 0; hf < 2; hf++) gp[mt][hf] = 0.f;

    #pragma unroll
    for (int mt = 0; mt < 2; mt++)
        #pragma unroll
        for (int nt = 0; nt < 8; nt++) {
            int c0 = wn * 64 + nt * 8 + 2 * t;
            #pragma unroll
            for (int hf = 0; hf < 2; hf++) {
                float o0 = gsm[c0]     * (acc[mt][nt][hf * 2 + 0] - mu[mt][hf]) * rs[mt][hf] + besm[c0];
                float o1 = gsm[c0 + 1] * (acc[mt][nt][hf * 2 + 1] - mu[mt][hf]) * rs[mt][hf] + besm[c0 + 1];
                gp[mt][hf] += o0 * qsm[c0] + o1 * qsm[c0 + 1];
                int r = r0 + wm * 32 + mt * 16 + g + hf * 8;
                if (r < NN) {
                    float2 o2 = make_float2(o0, o1);
                    *reinterpret_cast<float2*>(out + (size_t)r * HID + c0) = o2;
                }
            }
        }

    #pragma unroll
    for (int off = 1; off <= 2; off <<= 1)
        #pragma unroll
        for (int mt = 0; mt < 2; mt++)
            #pragma unroll
            for (int hf = 0; hf < 2; hf++)
                gp[mt][hf] += __shfl_xor_sync(0xffffffffu, gp[mt][hf], off);

    if (t == 0) {
        #pragma unroll
        for (int mt = 0; mt < 2; mt++)
            #pragma unroll
            for (int hf = 0; hf < 2; hf++) {
                int rl = wm * 32 + mt * 16 + g + hf * 8;
                stG[wn * 128 + rl] = gp[mt][hf];
            }
    }
    __syncthreads();

    if (wn == 0 && t == 0) {
        #pragma unroll
        for (int mt = 0; mt < 2; mt++)
            #pragma unroll
            for (int hf = 0; hf < 2; hf++) {
                int rl = wm * 32 + mt * 16 + g + hf * 8;
                int r = r0 + rl;
                if (r < NN) {
                    float z = stG[rl] + stG[128 + rl] + qbv - 1.0f;
                    s_out[r] = 1.0f / (1.0f + expf(-z));
                }
            }
    }
}

// ---------------- classifier: out = h @ cls_w + cls_b ----------------
__global__ void k_cls(const float* __restrict__ h, const float* __restrict__ cw,
                      const float* __restrict__ cb, float* __restrict__ out) {
    __shared__ float wsm[HID * OUTD];
    __shared__ float bsm[OUTD];
    for (int i = threadIdx.x; i < HID * OUTD; i += blockDim.x) wsm[i] = cw[i];
    if (threadIdx.x < OUTD) bsm[threadIdx.x] = cb[threadIdx.x];
    __syncthreads();

    int wid = (blockIdx.x * blockDim.x + threadIdx.x) >> 5;
    int lane = threadIdx.x & 31;
    if (wid >= NN) return;
    const float4 hv = *reinterpret_cast<const float4*>(h + (size_t)wid * HID + lane * 4);
    float hvv[4] = {hv.x, hv.y, hv.z, hv.w};
    float p[OUTD];
    #pragma unroll
    for (int j = 0; j < OUTD; j++) p[j] = 0.f;
    #pragma unroll
    for (int tq = 0; tq < 4; tq++) {
        int k = lane * 4 + tq;
        #pragma unroll
        for (int j = 0; j < OUTD; j++) p[j] += hvv[tq] * wsm[k * OUTD + j];
    }
    #pragma unroll
    for (int off = 16; off > 0; off >>= 1)
        #pragma unroll
        for (int j = 0; j < OUTD; j++) p[j] += __shfl_xor_sync(0xffffffffu, p[j], off);
    if (lane == 0) {
        #pragma unroll
        for (int j = 0; j < OUTD; j++) out[(size_t)wid * OUTD + j] = p[j] + bsm[j];
    }
}

// ---------------- launch ----------------
extern "C" void kernel_launch(void* const* d_in, const int* in_sizes, int n_in,
                              void* d_out, int out_size) {
    const float* x      = (const float*)d_in[0];
    const int*   ei     = (const int*)d_in[1];
    const float* W_proj = (const float*)d_in[2];
    const float* b_proj = (const float*)d_in[3];
    const float* gamma  = (const float*)d_in[4];
    const float* beta   = (const float*)d_in[5];
    const float* q_w    = (const float*)d_in[6];
    const float* q_b    = (const float*)d_in[7];
    const float* conv_w = (const float*)d_in[8];
    const float* cls_w  = (const float*)d_in[9];
    const float* cls_b  = (const float*)d_in[10];
    float* out = (float*)d_out;

    const int* row = ei;
    const int* col = ei + NE;

    float *h0, *h, *s, *dis, *eww;
    __nv_bfloat16 *suph, *supl, *xh, *xl, *wmh, *wml, *wph, *wpl;
    int *cnt, *cursor, *rowptr, *colw, *bsum, *boff;
    cudaGetSymbolAddress((void**)&h0, g_h0);
    cudaGetSymbolAddress((void**)&h, g_h);
    cudaGetSymbolAddress((void**)&suph, g_suph);
    cudaGetSymbolAddress((void**)&supl, g_supl);
    cudaGetSymbolAddress((void**)&xh, g_xh);
    cudaGetSymbolAddress((void**)&xl, g_xl);
    cudaGetSymbolAddress((void**)&s, g_s);
    cudaGetSymbolAddress((void**)&dis, g_dis);
    cudaGetSymbolAddress((void**)&cnt, g_cnt);
    cudaGetSymbolAddress((void**)&cursor, g_cursor);
    cudaGetSymbolAddress((void**)&rowptr, g_rowptr);
    cudaGetSymbolAddress((void**)&colw, g_colw);
    cudaGetSymbolAddress((void**)&eww, g_eww);
    cudaGetSymbolAddress((void**)&bsum, g_bsum);
    cudaGetSymbolAddress((void**)&boff, g_boff);
    cudaGetSymbolAddress((void**)&wmh, g_wmodh);
    cudaGetSymbolAddress((void**)&wml, g_wmodl);
    cudaGetSymbolAddress((void**)&wph, g_wprojh);
    cudaGetSymbolAddress((void**)&wpl, g_wprojl);

    cudaFuncSetAttribute(k_gemm_tc<IND, true>,
                         cudaFuncAttributeMaxDynamicSharedMemorySize, SMEM_BYTES);
    cudaFuncSetAttribute(k_gemm_tc<HID, false>,
                         cudaFuncAttributeMaxDynamicSharedMemorySize, SMEM_BYTES);

    const int TB = 256;
    const int gN  = (NN + TB - 1) / TB;
    const int gE  = (NE + TB - 1) / TB;
    const int gW  = (NN * 32 + TB - 1) / TB;    // warp-per-row grids
    const int gG  = (NN + 127) / 128;           // gemm grid (782)
    const int gX  = ((NN * IND / 4) + TB - 1) / TB;

    // order chosen so launch index 3 (the one ncu samples) is the proj GEMM
    k_prepx<<<gX, TB>>>(x, xh, xl);                                     // 0
    k_prepproj<<<(IND * HID + 255) / 256, 256>>>(W_proj, wph, wpl);     // 1
    k_zero<<<gN, TB>>>(cnt, cursor);                                    // 2
    k_gemm_tc<IND, true><<<gG, 256, SMEM_BYTES>>>(xh, xl, wph, wpl, b_proj,
                                                  gamma, beta, q_w, q_b, h0, s);  // 3
    k_hist<<<gE, TB>>>(row, cnt);                                       // 4
    k_dis<<<gN, TB>>>(cnt, dis);                                        // 5
    k_bsum<<<SCAN_NB, 256>>>(cnt, bsum);                                // 6
    k_bscan<<<1, 128>>>(bsum, boff);                                    // 7
    k_rowptr<<<SCAN_NB, 256>>>(cnt, boff, rowptr);                      // 8
    k_scatter<<<gE, TB>>>(row, col, rowptr, cursor, dis, colw, eww);    // 9
    k_prepw<<<(NL * HID * HID + 255) / 256, 256>>>(conv_w, wmh, wml);   // 10

    const float* hcur = h0;
    for (int i = 0; i < NL; i++) {
        k_spmm<<<gW, TB>>>(hcur, h0, s, rowptr, colw, eww, suph, supl);
        k_gemm_tc<HID, false><<<gG, 256, SMEM_BYTES>>>(suph, supl,
                                                       wmh + (size_t)i * HID * HID,
                                                       wml + (size_t)i * HID * HID,
                                                       nullptr, gamma, beta, q_w, q_b, h, s);
        hcur = h;
    }

    k_cls<<<gW, TB>>>(hcur, cls_w, cls_b, out);
}

// round 12
// speedup vs baseline: 1.6336x; 1.0371x over previous
#include <cuda_runtime.h>
#include <cuda_bf16.h>
#include <stdint.h>
#include <math.h>

#define NN   100000
#define NE   1600000
#define IND  256
#define HID  128
#define NL   4
#define OUTD 7
#define LN_EPS 1e-5f
#define SCAN_NB ((NN + 1023) / 1024)   // 98

// ---------------- scratch (device globals: no allocation allowed) ----------------
__device__ float g_h0[(size_t)NN * HID];
__device__ float g_h [(size_t)NN * HID];
__device__ __nv_bfloat16 g_suph[(size_t)NN * HID];
__device__ __nv_bfloat16 g_supl[(size_t)NN * HID];
__device__ float g_s[NN];
__device__ float g_dis[NN];
__device__ int   g_cnt[NN];
__device__ int   g_cursor[NN];
__device__ int   g_rowptr[NN + 1];
__device__ int   g_colw[NE];
__device__ float g_eww[NE];
__device__ int   g_bsum[SCAN_NB + 32];
__device__ int   g_boff[SCAN_NB + 32];
__device__ __nv_bfloat16 g_wmodh[(size_t)NL * HID * HID];   // [l][n][k]
__device__ __nv_bfloat16 g_wmodl[(size_t)NL * HID * HID];
__device__ __nv_bfloat16 g_wprojh[(size_t)HID * IND];       // [n][k]
__device__ __nv_bfloat16 g_wprojl[(size_t)HID * IND];

// ---------------- helpers ----------------
__device__ __forceinline__ void bf16split(float v, __nv_bfloat16& hi, __nv_bfloat16& lo) {
    hi = __float2bfloat16(v);
    lo = __float2bfloat16(v - __bfloat162float(hi));
}

// split a float2 (two consecutive k values) into packed bf16x2 hi and lo words
__device__ __forceinline__ void split2(float2 p, unsigned int& hi, unsigned int& lo) {
    __nv_bfloat16 h0, l0, h1, l1;
    bf16split(p.x, h0, l0);
    bf16split(p.y, h1, l1);
    __nv_bfloat162 hp = __halves2bfloat162(h0, h1);
    __nv_bfloat162 lp = __halves2bfloat162(l0, l1);
    hi = *reinterpret_cast<unsigned int*>(&hp);
    lo = *reinterpret_cast<unsigned int*>(&lp);
}

__device__ __forceinline__ void mma_bf16(float* d, const unsigned int* a, const unsigned int* b) {
    asm volatile(
        "mma.sync.aligned.m16n8k16.row.col.f32.bf16.bf16.f32 "
        "{%0,%1,%2,%3}, {%4,%5,%6,%7}, {%8,%9}, {%0,%1,%2,%3};\n"
        : "+f"(d[0]), "+f"(d[1]), "+f"(d[2]), "+f"(d[3])
        : "r"(a[0]), "r"(a[1]), "r"(a[2]), "r"(a[3]), "r"(b[0]), "r"(b[1]));
}

__device__ __forceinline__ void cp_async16(unsigned int smem_addr, const void* gptr, int src_sz) {
    asm volatile("cp.async.cg.shared.global [%0], [%1], 16, %2;\n"
                 :: "r"(smem_addr), "l"(gptr), "r"(src_sz));
}

// ---------------- weight prep ----------------
// W_proj [k][n] -> transposed bf16 planes [n][k]
__global__ void k_prepproj(const float* __restrict__ wp,
                           __nv_bfloat16* __restrict__ wh, __nv_bfloat16* __restrict__ wl) {
    int i = blockIdx.x * blockDim.x + threadIdx.x;
    if (i < IND * HID) {
        int n = i / IND, k = i - n * IND;
        float v = wp[(size_t)k * HID + n];
        __nv_bfloat16 hi, lo;
        bf16split(v, hi, lo);
        wh[i] = hi; wl[i] = lo;
    }
}

// W'[l] = theta_l*conv_w[l] + (1-theta_l)*I, transposed bf16 planes [l][n][k]
__global__ void k_prepw(const float* __restrict__ conv_w,
                        __nv_bfloat16* __restrict__ wh, __nv_bfloat16* __restrict__ wl) {
    int i = blockIdx.x * blockDim.x + threadIdx.x;
    if (i < NL * HID * HID) {
        int l = i / (HID * HID);
        int rc = i - l * (HID * HID);
        int n = rc >> 7, k = rc & 127;
        float theta = 0.5f / (float)(l + 1);
        float v = theta * conv_w[(size_t)l * HID * HID + k * HID + n];
        if (k == n) v += 1.0f - theta;
        __nv_bfloat16 hi, lo;
        bf16split(v, hi, lo);
        wh[i] = hi; wl[i] = lo;
    }
}

// ---------------- graph preprocessing ----------------
__global__ void k_zero(int* cnt, int* cursor) {
    int i = blockIdx.x * blockDim.x + threadIdx.x;
    if (i < NN) { cnt[i] = 0; cursor[i] = 0; }
}

__global__ void k_hist(const int* __restrict__ row, int* __restrict__ cnt) {
    int i = blockIdx.x * blockDim.x + threadIdx.x;
    if (i < NE) atomicAdd(&cnt[row[i]], 1);
}

__global__ void k_dis(const int* __restrict__ cnt, float* __restrict__ dis) {
    int i = blockIdx.x * blockDim.x + threadIdx.x;
    if (i < NN) {
        int c = cnt[i];
        float dg = (c == 0) ? 1.0f : (float)c;
        dis[i] = rsqrtf(dg);
    }
}

__global__ void k_bsum(const int* __restrict__ cnt, int* __restrict__ bsum) {
    __shared__ int sm[256];
    const int b = blockIdx.x, t = threadIdx.x;
    int base = b * 1024;
    int s = 0;
    #pragma unroll
    for (int q = 0; q < 4; q++) {
        int i = base + q * 256 + t;
        if (i < NN) s += cnt[i];
    }
    sm[t] = s;
    __syncthreads();
    for (int off = 128; off > 0; off >>= 1) {
        if (t < off) sm[t] += sm[t + off];
        __syncthreads();
    }
    if (t == 0) bsum[b] = sm[0];
}

__global__ void k_bscan(const int* __restrict__ bsum, int* __restrict__ boff) {
    __shared__ int sm[128];
    int t = threadIdx.x;
    sm[t] = (t < SCAN_NB) ? bsum[t] : 0;
    __syncthreads();
    for (int off = 1; off < 128; off <<= 1) {
        int v = (t >= off) ? sm[t - off] : 0;
        __syncthreads();
        sm[t] += v;
        __syncthreads();
    }
    if (t < SCAN_NB) boff[t] = (t == 0) ? 0 : sm[t - 1];
}

__global__ void k_rowptr(const int* __restrict__ cnt, const int* __restrict__ boff,
                         int* __restrict__ rowptr) {
    __shared__ int sm[256];
    const int b = blockIdx.x, t = threadIdx.x;
    int base = b * 1024;
    int vals[4];
    int s = 0;
    #pragma unroll
    for (int q = 0; q < 4; q++) {
        int i = base + t * 4 + q;
        vals[q] = (i < NN) ? cnt[i] : 0;
        s += vals[q];
    }
    sm[t] = s;
    __syncthreads();
    for (int off = 1; off < 256; off <<= 1) {
        int v = (t >= off) ? sm[t - off] : 0;
        __syncthreads();
        sm[t] += v;
        __syncthreads();
    }
    int run = boff[b] + ((t == 0) ? 0 : sm[t - 1]);
    #pragma unroll
    for (int q = 0; q < 4; q++) {
        int i = base + t * 4 + q;
        if (i < NN) rowptr[i] = run;
        run += vals[q];
    }
    if (b == 0 && t == 0) rowptr[NN] = NE;
}

__global__ void k_scatter(const int* __restrict__ row, const int* __restrict__ col,
                          const int* __restrict__ rowptr, int* __restrict__ cursor,
                          const float* __restrict__ dis,
                          int* __restrict__ colw, float* __restrict__ eww) {
    int i = blockIdx.x * blockDim.x + threadIdx.x;
    if (i < NE) {
        int r = row[i], c = col[i];
        int pos = rowptr[r] + atomicAdd(&cursor[r], 1);
        colw[pos] = c;
        eww[pos] = dis[r] * dis[c];
    }
}

// ---------------- SpMM + AOR blend, output pre-split into bf16 hi/lo planes ----------------
__global__ void k_spmm(const float* __restrict__ h, const float* __restrict__ h0,
                       const float* __restrict__ s, const int* __restrict__ rowptr,
                       const int* __restrict__ colw, const float* __restrict__ eww,
                       __nv_bfloat16* __restrict__ suph, __nv_bfloat16* __restrict__ supl) {
    int wid = (blockIdx.x * blockDim.x + threadIdx.x) >> 5;
    int lane = threadIdx.x & 31;
    if (wid >= NN) return;
    int start = rowptr[wid], end = rowptr[wid + 1];
    float ax = 0.f, ay = 0.f, az = 0.f, aw = 0.f;
    for (int e0 = start; e0 < end; e0 += 32) {
        int n = end - e0; if (n > 32) n = 32;
        int c = 0; float w = 0.f;
        if (lane < n) { c = colw[e0 + lane]; w = eww[e0 + lane]; }
        for (int j = 0; j < n; j++) {
            int cj   = __shfl_sync(0xffffffffu, c, j);
            float wj = __shfl_sync(0xffffffffu, w, j);
            const float4 hv = *reinterpret_cast<const float4*>(h + (size_t)cj * HID + lane * 4);
            ax += wj * hv.x; ay += wj * hv.y; az += wj * hv.z; aw += wj * hv.w;
        }
    }
    float sr = s[wid];
    float om = 1.0f - sr;
    const float4 h0v = *reinterpret_cast<const float4*>(h0 + (size_t)wid * HID + lane * 4);
    float vx = om * ax + sr * h0v.x;
    float vy = om * ay + sr * h0v.y;
    float vz = om * az + sr * h0v.z;
    float vw = om * aw + sr * h0v.w;
    unsigned int h01, l01, h23, l23;
    split2(make_float2(vx, vy), h01, l01);
    split2(make_float2(vz, vw), h23, l23);
    uint2 ho, lo2;
    ho.x = h01; ho.y = h23;
    lo2.x = l01; lo2.y = l23;
    *reinterpret_cast<uint2*>(suph + (size_t)wid * HID + lane * 4) = ho;
    *reinterpret_cast<uint2*>(supl + (size_t)wid * HID + lane * 4) = lo2;
}

// ---------------- 3xBF16 tensor-core GEMM (m16n8k16) + LN + gate epilogue ----------------
// PROJ : out = LN(x @ W + bias)   — A = fp32 x, split to bf16 hi/lo at fragment load
// else : out = LN(relu(A @ W'))  — A pre-split bf16 planes
// s_out = sigmoid(out @ q_w + q_b - 1)
// W always pre-split bf16, transposed [n][k]. A·B = Ah·Bh + Ah·Bl + Al·Bh.
#define KC 16                 // K per chunk = one m16n8k16
#define PITCH 24              // bf16 row pitch
#define APF 20                // fp32 A row pitch (PROJ)
#define PLANE_B (128 * PITCH * 2)       // 6144 bytes per bf16 plane-buffer
#define APLANE_B (128 * APF * 4)        // 10240 bytes per fp32 A buffer (PROJ, fits in A region)
#define O_AH 0
#define O_AL (2 * PLANE_B)
#define O_BH (4 * PLANE_B)
#define O_BL (6 * PLANE_B)
#define O_FLT (8 * PLANE_B)             // 49152: float region
#define SMEM_BYTES (O_FLT + (256 * 3 + 512) * 4)   // 54272

template<int K, bool PROJ>
__launch_bounds__(256)
__global__ void k_gemm_tc(const __nv_bfloat16* __restrict__ Ah, const __nv_bfloat16* __restrict__ Al,
                          const float* __restrict__ Ax,
                          const __nv_bfloat16* __restrict__ Wh, const __nv_bfloat16* __restrict__ Wl,
                          const float* __restrict__ bias,
                          const float* __restrict__ gamma, const float* __restrict__ beta,
                          const float* __restrict__ qw, const float* __restrict__ qb,
                          float* __restrict__ out, float* __restrict__ s_out) {
    constexpr int NK = K / KC;
    extern __shared__ char smc[];
    float* fl  = (float*)(smc + O_FLT);
    float* stS = fl;
    float* stQ = fl + 256;
    float* stG = fl + 512;
    float* gsm = fl + 768;
    float* besm = gsm + 128;
    float* qsm  = gsm + 256;
    float* bism = gsm + 384;

    const int tid = threadIdx.x;
    const int lane = tid & 31;
    const int warp = tid >> 5;
    const int wm = warp & 3;          // rows wm*32
    const int wn = warp >> 2;         // cols wn*64
    const int g  = lane >> 2;
    const int t  = lane & 3;
    const int r0 = blockIdx.x * 128;
    const float qbv = qb[0];

    if (tid < 128) {
        gsm[tid]  = gamma[tid];
        besm[tid] = beta[tid];
        qsm[tid]  = qw[tid];
        bism[tid] = PROJ ? bias[tid] : 0.f;
    }

    // cp.async mappings
    const int crow = tid >> 1, chalf = tid & 1;   // bf16 planes: 1 chunk/thread/plane
    const int xrow0 = tid >> 2, xq0 = tid & 3;    // PROJ fp32 A: 2 chunks/thread
    const int xrow1 = (tid + 256) >> 2, xq1 = (tid + 256) & 3;

    auto issue = [&](int kt, int buf) {
        unsigned int d;
        if (PROJ) {
            int sz0 = (r0 + xrow0 < NN) ? 16 : 0;
            int sz1 = (r0 + xrow1 < NN) ? 16 : 0;
            d = (unsigned int)__cvta_generic_to_shared(smc + O_AH + buf * APLANE_B + xrow0 * (APF * 4) + xq0 * 16);
            cp_async16(d, Ax + (size_t)(r0 + xrow0) * K + kt + xq0 * 4, sz0);
            d = (unsigned int)__cvta_generic_to_shared(smc + O_AH + buf * APLANE_B + xrow1 * (APF * 4) + xq1 * 16);
            cp_async16(d, Ax + (size_t)(r0 + xrow1) * K + kt + xq1 * 4, sz1);
        } else {
            const int dof = crow * (PITCH * 2) + chalf * 16;
            const int soff = kt + chalf * 8;
            int szA = (r0 + crow < NN) ? 16 : 0;
            d = (unsigned int)__cvta_generic_to_shared(smc + O_AH + buf * PLANE_B + dof);
            cp_async16(d, Ah + (size_t)(r0 + crow) * K + soff, szA);
            d = (unsigned int)__cvta_generic_to_shared(smc + O_AL + buf * PLANE_B + dof);
            cp_async16(d, Al + (size_t)(r0 + crow) * K + soff, szA);
        }
        {
            const int dof = crow * (PITCH * 2) + chalf * 16;
            const int soff = kt + chalf * 8;
            d = (unsigned int)__cvta_generic_to_shared(smc + O_BH + buf * PLANE_B + dof);
            cp_async16(d, Wh + (size_t)crow * K + soff, 16);
            d = (unsigned int)__cvta_generic_to_shared(smc + O_BL + buf * PLANE_B + dof);
            cp_async16(d, Wl + (size_t)crow * K + soff, 16);
        }
        asm volatile("cp.async.commit_group;\n");
    };

    float acc[2][8][4];
    #pragma unroll
    for (int mt = 0; mt < 2; mt++)
        #pragma unroll
        for (int nt = 0; nt < 8; nt++)
            #pragma unroll
            for (int q = 0; q < 4; q++) acc[mt][nt][q] = 0.f;

    issue(0, 0);

    #pragma unroll
    for (int i = 0; i < NK; i++) {
        if (i + 1 < NK) {
            issue((i + 1) * KC, (i + 1) & 1);
            asm volatile("cp.async.wait_group 1;\n");
        } else {
            asm volatile("cp.async.wait_group 0;\n");
        }
        __syncthreads();

        unsigned int afh[2][4], afl[2][4];
        if (PROJ) {
            const float* af32 = (const float*)(smc + O_AH + (i & 1) * APLANE_B);
            #pragma unroll
            for (int mt = 0; mt < 2; mt++) {
                const int rA = (wm * 32 + mt * 16 + g) * APF;
                const int rB = rA + 8 * APF;
                float2 p0 = *(const float2*)&af32[rA + 2 * t];
                float2 p1 = *(const float2*)&af32[rB + 2 * t];
                float2 p2 = *(const float2*)&af32[rA + 8 + 2 * t];
                float2 p3 = *(const float2*)&af32[rB + 8 + 2 * t];
                split2(p0, afh[mt][0], afl[mt][0]);
                split2(p1, afh[mt][1], afl[mt][1]);
                split2(p2, afh[mt][2], afl[mt][2]);
                split2(p3, afh[mt][3], afl[mt][3]);
            }
        } else {
            const int bo = (i & 1) * PLANE_B;
            const __nv_bfloat16* ash = (const __nv_bfloat16*)(smc + O_AH + bo);
            const __nv_bfloat16* asl = (const __nv_bfloat16*)(smc + O_AL + bo);
            #pragma unroll
            for (int mt = 0; mt < 2; mt++) {
                const int r1 = (wm * 32 + mt * 16 + g) * PITCH;
                const int r2 = r1 + 8 * PITCH;
                afh[mt][0] = *(const unsigned int*)&ash[r1 + 2 * t];
                afh[mt][1] = *(const unsigned int*)&ash[r2 + 2 * t];
                afh[mt][2] = *(const unsigned int*)&ash[r1 + 8 + 2 * t];
                afh[mt][3] = *(const unsigned int*)&ash[r2 + 8 + 2 * t];
                afl[mt][0] = *(const unsigned int*)&asl[r1 + 2 * t];
                afl[mt][1] = *(const unsigned int*)&asl[r2 + 2 * t];
                afl[mt][2] = *(const unsigned int*)&asl[r1 + 8 + 2 * t];
                afl[mt][3] = *(const unsigned int*)&asl[r2 + 8 + 2 * t];
            }
        }
        const int bo = (i & 1) * PLANE_B;
        const __nv_bfloat16* bsh = (const __nv_bfloat16*)(smc + O_BH + bo);
        const __nv_bfloat16* bsl = (const __nv_bfloat16*)(smc + O_BL + bo);
        unsigned int bfh[8][2], bfl[8][2];
        #pragma unroll
        for (int nt = 0; nt < 8; nt++) {
            const int nb = (wn * 64 + nt * 8 + g) * PITCH;
            bfh[nt][0] = *(const unsigned int*)&bsh[nb + 2 * t];
            bfh[nt][1] = *(const unsigned int*)&bsh[nb + 8 + 2 * t];
            bfl[nt][0] = *(const unsigned int*)&bsl[nb + 2 * t];
            bfl[nt][1] = *(const unsigned int*)&bsl[nb + 8 + 2 * t];
        }
        #pragma unroll
        for (int mt = 0; mt < 2; mt++)
            #pragma unroll
            for (int nt = 0; nt < 8; nt++) {
                mma_bf16(acc[mt][nt], afh[mt], bfl[nt]);   // hi*lo
                mma_bf16(acc[mt][nt], afl[mt], bfh[nt]);   // lo*hi
                mma_bf16(acc[mt][nt], afh[mt], bfh[nt]);   // hi*hi (largest last)
            }
        __syncthreads();
    }

    // ---- epilogue in fragment layout ----
    float vsum[2][2], vsq[2][2];
    #pragma unroll
    for (int mt = 0; mt < 2; mt++)
        #pragma unroll
        for (int hf = 0; hf < 2; hf++) { vsum[mt][hf] = 0.f; vsq[mt][hf] = 0.f; }

    #pragma unroll
    for (int mt = 0; mt < 2; mt++)
        #pragma unroll
        for (int nt = 0; nt < 8; nt++) {
            int c0 = wn * 64 + nt * 8 + 2 * t;
            #pragma unroll
            for (int q = 0; q < 4; q++) {
                int col = c0 + (q & 1);
                float v = acc[mt][nt][q];
                v = PROJ ? (v + bism[col]) : fmaxf(v, 0.f);
                acc[mt][nt][q] = v;
                int hf = q >> 1;
                vsum[mt][hf] += v;
                vsq[mt][hf]  += v * v;
            }
        }

    #pragma unroll
    for (int off = 1; off <= 2; off <<= 1)
        #pragma unroll
        for (int mt = 0; mt < 2; mt++)
            #pragma unroll
            for (int hf = 0; hf < 2; hf++) {
                vsum[mt][hf] += __shfl_xor_sync(0xffffffffu, vsum[mt][hf], off);
                vsq[mt][hf]  += __shfl_xor_sync(0xffffffffu, vsq[mt][hf],  off);
            }

    if (t == 0) {
        #pragma unroll
        for (int mt = 0; mt < 2; mt++)
            #pragma unroll
            for (int hf = 0; hf < 2; hf++) {
                int rl = wm * 32 + mt * 16 + g + hf * 8;
                stS[wn * 128 + rl] = vsum[mt][hf];
                stQ[wn * 128 + rl] = vsq[mt][hf];
            }
    }
    __syncthreads();

    float mu[2][2], rs[2][2];
    #pragma unroll
    for (int mt = 0; mt < 2; mt++)
        #pragma unroll
        for (int hf = 0; hf < 2; hf++) {
            int rl = wm * 32 + mt * 16 + g + hf * 8;
            float sm = stS[rl] + stS[128 + rl];
            float sq = stQ[rl] + stQ[128 + rl];
            float m = sm * (1.0f / 128.0f);
            float var = sq * (1.0f / 128.0f) - m * m;
            var = fmaxf(var, 0.f);
            mu[mt][hf] = m;
            rs[mt][hf] = rsqrtf(var + LN_EPS);
        }

    float gp[2][2];
    #pragma unroll
    for (int mt = 0; mt < 2; mt++)
        #pragma unroll
        for (int hf = 0; hf < 2; hf++) gp[mt][hf] = 0.f;

    #pragma unroll
    for (int mt = 0; mt < 2; mt++)
        #pragma unroll
        for (int nt = 0; nt < 8; nt++) {
            int c0 = wn * 64 + nt * 8 + 2 * t;
            #pragma unroll
            for (int hf = 0; hf < 2; hf++) {
                float o0 = gsm[c0]     * (acc[mt][nt][hf * 2 + 0] - mu[mt][hf]) * rs[mt][hf] + besm[c0];
                float o1 = gsm[c0 + 1] * (acc[mt][nt][hf * 2 + 1] - mu[mt][hf]) * rs[mt][hf] + besm[c0 + 1];
                gp[mt][hf] += o0 * qsm[c0] + o1 * qsm[c0 + 1];
                int r = r0 + wm * 32 + mt * 16 + g + hf * 8;
                if (r < NN) {
                    float2 o2 = make_float2(o0, o1);
                    *reinterpret_cast<float2*>(out + (size_t)r * HID + c0) = o2;
                }
            }
        }

    #pragma unroll
    for (int off = 1; off <= 2; off <<= 1)
        #pragma unroll
        for (int mt = 0; mt < 2; mt++)
            #pragma unroll
            for (int hf = 0; hf < 2; hf++)
                gp[mt][hf] += __shfl_xor_sync(0xffffffffu, gp[mt][hf], off);

    if (t == 0) {
        #pragma unroll
        for (int mt = 0; mt < 2; mt++)
            #pragma unroll
            for (int hf = 0; hf < 2; hf++) {
                int rl = wm * 32 + mt * 16 + g + hf * 8;
                stG[wn * 128 + rl] = gp[mt][hf];
            }
    }
    __syncthreads();

    if (wn == 0 && t == 0) {
        #pragma unroll
        for (int mt = 0; mt < 2; mt++)
            #pragma unroll
            for (int hf = 0; hf < 2; hf++) {
                int rl = wm * 32 + mt * 16 + g + hf * 8;
                int r = r0 + rl;
                if (r < NN) {
                    float z = stG[rl] + stG[128 + rl] + qbv - 1.0f;
                    s_out[r] = 1.0f / (1.0f + expf(-z));
                }
            }
    }
}

// ---------------- classifier: out = h @ cls_w + cls_b ----------------
__global__ void k_cls(const float* __restrict__ h, const float* __restrict__ cw,
                      const float* __restrict__ cb, float* __restrict__ out) {
    __shared__ float wsm[HID * OUTD];
    __shared__ float bsm[OUTD];
    for (int i = threadIdx.x; i < HID * OUTD; i += blockDim.x) wsm[i] = cw[i];
    if (threadIdx.x < OUTD) bsm[threadIdx.x] = cb[threadIdx.x];
    __syncthreads();

    int wid = (blockIdx.x * blockDim.x + threadIdx.x) >> 5;
    int lane = threadIdx.x & 31;
    if (wid >= NN) return;
    const float4 hv = *reinterpret_cast<const float4*>(h + (size_t)wid * HID + lane * 4);
    float hvv[4] = {hv.x, hv.y, hv.z, hv.w};
    float p[OUTD];
    #pragma unroll
    for (int j = 0; j < OUTD; j++) p[j] = 0.f;
    #pragma unroll
    for (int tq = 0; tq < 4; tq++) {
        int k = lane * 4 + tq;
        #pragma unroll
        for (int j = 0; j < OUTD; j++) p[j] += hvv[tq] * wsm[k * OUTD + j];
    }
    #pragma unroll
    for (int off = 16; off > 0; off >>= 1)
        #pragma unroll
        for (int j = 0; j < OUTD; j++) p[j] += __shfl_xor_sync(0xffffffffu, p[j], off);
    if (lane == 0) {
        #pragma unroll
        for (int j = 0; j < OUTD; j++) out[(size_t)wid * OUTD + j] = p[j] + bsm[j];
    }
}

// ---------------- launch ----------------
extern "C" void kernel_launch(void* const* d_in, const int* in_sizes, int n_in,
                              void* d_out, int out_size) {
    const float* x      = (const float*)d_in[0];
    const int*   ei     = (const int*)d_in[1];
    const float* W_proj = (const float*)d_in[2];
    const float* b_proj = (const float*)d_in[3];
    const float* gamma  = (const float*)d_in[4];
    const float* beta   = (const float*)d_in[5];
    const float* q_w    = (const float*)d_in[6];
    const float* q_b    = (const float*)d_in[7];
    const float* conv_w = (const float*)d_in[8];
    const float* cls_w  = (const float*)d_in[9];
    const float* cls_b  = (const float*)d_in[10];
    float* out = (float*)d_out;

    const int* row = ei;
    const int* col = ei + NE;

    float *h0, *h, *s, *dis, *eww;
    __nv_bfloat16 *suph, *supl, *wmh, *wml, *wph, *wpl;
    int *cnt, *cursor, *rowptr, *colw, *bsum, *boff;
    cudaGetSymbolAddress((void**)&h0, g_h0);
    cudaGetSymbolAddress((void**)&h, g_h);
    cudaGetSymbolAddress((void**)&suph, g_suph);
    cudaGetSymbolAddress((void**)&supl, g_supl);
    cudaGetSymbolAddress((void**)&s, g_s);
    cudaGetSymbolAddress((void**)&dis, g_dis);
    cudaGetSymbolAddress((void**)&cnt, g_cnt);
    cudaGetSymbolAddress((void**)&cursor, g_cursor);
    cudaGetSymbolAddress((void**)&rowptr, g_rowptr);
    cudaGetSymbolAddress((void**)&colw, g_colw);
    cudaGetSymbolAddress((void**)&eww, g_eww);
    cudaGetSymbolAddress((void**)&bsum, g_bsum);
    cudaGetSymbolAddress((void**)&boff, g_boff);
    cudaGetSymbolAddress((void**)&wmh, g_wmodh);
    cudaGetSymbolAddress((void**)&wml, g_wmodl);
    cudaGetSymbolAddress((void**)&wph, g_wprojh);
    cudaGetSymbolAddress((void**)&wpl, g_wprojl);

    cudaFuncSetAttribute(k_gemm_tc<IND, true>,
                         cudaFuncAttributeMaxDynamicSharedMemorySize, SMEM_BYTES);
    cudaFuncSetAttribute(k_gemm_tc<HID, false>,
                         cudaFuncAttributeMaxDynamicSharedMemorySize, SMEM_BYTES);

    const int TB = 256;
    const int gN  = (NN + TB - 1) / TB;
    const int gE  = (NE + TB - 1) / TB;
    const int gW  = (NN * 32 + TB - 1) / TB;    // warp-per-row grids
    const int gG  = (NN + 127) / 128;           // gemm grid (782)

    // Fork a side stream so the CSR build overlaps the proj GEMM chain.
    // Stream/event objects are host-side resources (no device memory); they are
    // intentionally NOT destroyed here (destroying mid-capture would invalidate
    // the graph; kernel_launch is only invoked for the correctness run and the
    // single capture, so at most two small host objects are retained).
    cudaStream_t s1;
    cudaStreamCreateWithFlags(&s1, cudaStreamNonBlocking);
    cudaEvent_t evF, evJ;
    cudaEventCreateWithFlags(&evF, cudaEventDisableTiming);
    cudaEventCreateWithFlags(&evJ, cudaEventDisableTiming);

    cudaEventRecord(evF, 0);
    cudaStreamWaitEvent(s1, evF, 0);

    // branch B (side stream): CSR build + layer-weight prep
    k_zero<<<gN, TB, 0, s1>>>(cnt, cursor);                                   // 0
    k_hist<<<gE, TB, 0, s1>>>(row, cnt);                                      // 1
    // branch A (main stream): proj weights + proj GEMM (in-kernel x split)
    k_prepproj<<<(IND * HID + 255) / 256, 256>>>(W_proj, wph, wpl);           // 2
    k_gemm_tc<IND, true><<<gG, 256, SMEM_BYTES>>>(nullptr, nullptr, x, wph, wpl,
                                                  b_proj, gamma, beta, q_w, q_b, h0, s); // 3
    k_dis<<<gN, TB, 0, s1>>>(cnt, dis);                                       // 4
    k_bsum<<<SCAN_NB, 256, 0, s1>>>(cnt, bsum);                               // 5
    k_bscan<<<1, 128, 0, s1>>>(bsum, boff);                                   // 6
    k_rowptr<<<SCAN_NB, 256, 0, s1>>>(cnt, boff, rowptr);                     // 7
    k_scatter<<<gE, TB, 0, s1>>>(row, col, rowptr, cursor, dis, colw, eww);   // 8
    k_prepw<<<(NL * HID * HID + 255) / 256, 256, 0, s1>>>(conv_w, wmh, wml);  // 9

    cudaEventRecord(evJ, s1);
    cudaStreamWaitEvent(0, evJ, 0);

    const float* hcur = h0;
    for (int i = 0; i < NL; i++) {
        k_spmm<<<gW, TB>>>(hcur, h0, s, rowptr, colw, eww, suph, supl);
        k_gemm_tc<HID, false><<<gG, 256, SMEM_BYTES>>>(suph, supl, nullptr,
                                                       wmh + (size_t)i * HID * HID,
                                                       wml + (size_t)i * HID * HID,
                                                       nullptr, gamma, beta, q_w, q_b, h, s);
        hcur = h;
    }

    k_cls<<<gW, TB>>>(hcur, cls_w, cls_b, out);
}